// round 8
// baseline (speedup 1.0000x reference)
#include <cuda_runtime.h>
#include <cuda_bf16.h>
#include <math.h>
#include <stdint.h>
#include <stddef.h>

// Problem dims
#define Bsz 256
#define Ssz 512
#define Fdim 128
#define Hdim 128
#define G3  384   // 3*H

// Output layout (tuple flattened): h_enc, output, z, gamma, dis, dis_perm
#define OFF_HENC  ((size_t)0)
#define OFF_OUT   ((size_t)32768)                       // 256*128
#define OFF_Z     ((size_t)(32768 + 16777216))          // + 256*512*128
#define OFF_GAMMA ((size_t)(OFF_Z + 256*129))
#define OFF_DIS   ((size_t)(OFF_GAMMA + 256*4))
#define OFF_DISP  ((size_t)(OFF_DIS + 256*8*128))

typedef unsigned long long ull;

// Scratch (device globals; no allocations allowed)
__device__ float g_Genc[(size_t)Ssz * Bsz * G3];    // [t][b][g]  192 MB
__device__ float g_Hdec[(size_t)Ssz * Bsz * Hdim];  // [i][b][j]   64 MB
__device__ float g_Henc[Bsz * Hdim];
__device__ float g_Mf[G3 * Hdim];
__device__ float g_bf[G3];
__device__ int   g_perm[8 * Bsz];                   // [k][pos] -> batch idx

__device__ __forceinline__ float sigf(float x) { return 1.0f / (1.0f + expf(-x)); }

// ---- packed f32x2 helpers (FFMA2 only reachable via PTX fma.rn.f32x2) ----
__device__ __forceinline__ ull pk2(float lo, float hi) {
    ull r; asm("mov.b64 %0, {%1, %2};" : "=l"(r) : "f"(lo), "f"(hi)); return r;
}
__device__ __forceinline__ ull f2fma(ull a, ull b, ull c) {
    ull d; asm("fma.rn.f32x2 %0, %1, %2, %3;" : "=l"(d) : "l"(a), "l"(b), "l"(c)); return d;
}
__device__ __forceinline__ float psum(ull v) {
    float a, b; asm("mov.b64 {%0, %1}, %2;" : "=f"(a), "=f"(b) : "l"(v)); return a + b;
}

// ---------------------------------------------------------------------------
// Threefry2x32 core (20 rounds, exact JAX constants)
// ---------------------------------------------------------------------------
__device__ __forceinline__ uint2 threefry(unsigned k0, unsigned k1,
                                          unsigned x0, unsigned x1) {
    unsigned ks2 = k0 ^ k1 ^ 0x1BD11BDAu;
    x0 += k0; x1 += k1;
#define TFR(r) { x0 += x1; x1 = (x1 << (r)) | (x1 >> (32 - (r))); x1 ^= x0; }
    TFR(13) TFR(15) TFR(26) TFR(6)   x0 += k1;  x1 += ks2 + 1u;
    TFR(17) TFR(29) TFR(16) TFR(24)  x0 += ks2; x1 += k0 + 2u;
    TFR(13) TFR(15) TFR(26) TFR(6)   x0 += k0;  x1 += k1 + 3u;
    TFR(17) TFR(29) TFR(16) TFR(24)  x0 += k1;  x1 += ks2 + 4u;
    TFR(13) TFR(15) TFR(26) TFR(6)   x0 += ks2; x1 += k0 + 5u;
#undef TFR
    return make_uint2(x0, x1);
}

// JAX threefry_partitionable=True reproduction (verified passing in R5)
__global__ void perm_kernel(int* __restrict__ perm) {
    __shared__ unsigned sk[8][2];
    __shared__ unsigned bits[256];
    int t = threadIdx.x;
    if (t < 8) {
        uint2 pk = threefry(0u, 42u, 0u, (unsigned)t);   // perm_keys[t]
        uint2 s  = threefry(pk.x, pk.y, 0u, 1u);         // subkey = split(.)[1]
        sk[t][0] = s.x; sk[t][1] = s.y;
    }
    __syncthreads();
    for (int k = 0; k < 8; k++) {
        uint2 y = threefry(sk[k][0], sk[k][1], 0u, (unsigned)t);
        bits[t] = y.x ^ y.y;
        __syncthreads();
        unsigned mine = bits[t];
        int rank = 0;
        for (int j = 0; j < 256; j++) {
            unsigned o = bits[j];
            rank += (o < mine) || (o == mine && j < t);
        }
        perm[k * 256 + rank] = t;
        __syncthreads();
    }
}

// ---------------------------------------------------------------------------
// GEMM A (R5-exact, best measured): g_Genc[r][g] = x . enc_Wih[g,:] + bias
// ---------------------------------------------------------------------------
__global__ void __launch_bounds__(256) gemm_gi(const float* __restrict__ X,
                                               const float* __restrict__ W,
                                               const float* __restrict__ bias) {
    __shared__ float As[32 * 64];
    __shared__ float Bs[32 * 64];
    int tid = threadIdx.x;
    int tx = tid & 15, ty = tid >> 4;
    int rBase = blockIdx.x * 64;
    int n0 = blockIdx.y * 64;
    float acc[4][4];
#pragma unroll
    for (int i = 0; i < 4; i++)
#pragma unroll
        for (int j = 0; j < 4; j++) acc[i][j] = 0.0f;

    for (int kc = 0; kc < 4; kc++) {
        int k0 = kc * 32;
#pragma unroll
        for (int p = 0; p < 2; p++) {
            int l = tid + p * 256;
            int row = l >> 3, q = l & 7;
            int r = rBase + row;
            const float* xp = X + (((size_t)(r & 255) * 512 + (r >> 8)) << 7);
            float4 v = *(const float4*)&xp[k0 + q * 4];
            As[(q * 4 + 0) * 64 + row] = v.x;
            As[(q * 4 + 1) * 64 + row] = v.y;
            As[(q * 4 + 2) * 64 + row] = v.z;
            As[(q * 4 + 3) * 64 + row] = v.w;
        }
#pragma unroll
        for (int p = 0; p < 2; p++) {
            int l = tid + p * 256;
            int n = l >> 3, q = l & 7;
            float4 v = *(const float4*)&W[(size_t)(n0 + n) * 128 + k0 + q * 4];
            Bs[(q * 4 + 0) * 64 + n] = v.x;
            Bs[(q * 4 + 1) * 64 + n] = v.y;
            Bs[(q * 4 + 2) * 64 + n] = v.z;
            Bs[(q * 4 + 3) * 64 + n] = v.w;
        }
        __syncthreads();
#pragma unroll
        for (int kk = 0; kk < 32; kk++) {
            float4 a = *(const float4*)&As[kk * 64 + ty * 4];
            float4 b = *(const float4*)&Bs[kk * 64 + tx * 4];
            acc[0][0] = fmaf(a.x, b.x, acc[0][0]); acc[0][1] = fmaf(a.x, b.y, acc[0][1]);
            acc[0][2] = fmaf(a.x, b.z, acc[0][2]); acc[0][3] = fmaf(a.x, b.w, acc[0][3]);
            acc[1][0] = fmaf(a.y, b.x, acc[1][0]); acc[1][1] = fmaf(a.y, b.y, acc[1][1]);
            acc[1][2] = fmaf(a.y, b.z, acc[1][2]); acc[1][3] = fmaf(a.y, b.w, acc[1][3]);
            acc[2][0] = fmaf(a.z, b.x, acc[2][0]); acc[2][1] = fmaf(a.z, b.y, acc[2][1]);
            acc[2][2] = fmaf(a.z, b.z, acc[2][2]); acc[2][3] = fmaf(a.z, b.w, acc[2][3]);
            acc[3][0] = fmaf(a.w, b.x, acc[3][0]); acc[3][1] = fmaf(a.w, b.y, acc[3][1]);
            acc[3][2] = fmaf(a.w, b.z, acc[3][2]); acc[3][3] = fmaf(a.w, b.w, acc[3][3]);
        }
        __syncthreads();
    }
    float b0 = bias[n0 + tx * 4 + 0], b1 = bias[n0 + tx * 4 + 1];
    float b2 = bias[n0 + tx * 4 + 2], b3 = bias[n0 + tx * 4 + 3];
#pragma unroll
    for (int i = 0; i < 4; i++) {
        int r = rBase + ty * 4 + i;
        float4 v = make_float4(acc[i][0] + b0, acc[i][1] + b1, acc[i][2] + b2, acc[i][3] + b3);
        *(float4*)&g_Genc[(size_t)r * 384 + n0 + tx * 4] = v;
    }
}

// ---------------------------------------------------------------------------
// out-GEMM (R5-exact): o_i = Hdec[i] @ out_W^T + out_b ; writes output[b][511-i][:]
// ---------------------------------------------------------------------------
__global__ void __launch_bounds__(256) gemm_out(const float* __restrict__ W,
                                                const float* __restrict__ bias,
                                                float* __restrict__ out) {
    __shared__ float As[32 * 64];
    __shared__ float Bs[32 * 64];
    int tid = threadIdx.x;
    int tx = tid & 15, ty = tid >> 4;
    int rBase = blockIdx.x * 64;
    int n0 = blockIdx.y * 64;
    float acc[4][4];
#pragma unroll
    for (int i = 0; i < 4; i++)
#pragma unroll
        for (int j = 0; j < 4; j++) acc[i][j] = 0.0f;

    for (int kc = 0; kc < 4; kc++) {
        int k0 = kc * 32;
#pragma unroll
        for (int p = 0; p < 2; p++) {
            int l = tid + p * 256;
            int row = l >> 3, q = l & 7;
            int r = rBase + row;
            float4 v = *(const float4*)&g_Hdec[(size_t)r * 128 + k0 + q * 4];
            As[(q * 4 + 0) * 64 + row] = v.x;
            As[(q * 4 + 1) * 64 + row] = v.y;
            As[(q * 4 + 2) * 64 + row] = v.z;
            As[(q * 4 + 3) * 64 + row] = v.w;
        }
#pragma unroll
        for (int p = 0; p < 2; p++) {
            int l = tid + p * 256;
            int n = l >> 3, q = l & 7;
            float4 v = *(const float4*)&W[(size_t)(n0 + n) * 128 + k0 + q * 4];
            Bs[(q * 4 + 0) * 64 + n] = v.x;
            Bs[(q * 4 + 1) * 64 + n] = v.y;
            Bs[(q * 4 + 2) * 64 + n] = v.z;
            Bs[(q * 4 + 3) * 64 + n] = v.w;
        }
        __syncthreads();
#pragma unroll
        for (int kk = 0; kk < 32; kk++) {
            float4 a = *(const float4*)&As[kk * 64 + ty * 4];
            float4 b = *(const float4*)&Bs[kk * 64 + tx * 4];
            acc[0][0] = fmaf(a.x, b.x, acc[0][0]); acc[0][1] = fmaf(a.x, b.y, acc[0][1]);
            acc[0][2] = fmaf(a.x, b.z, acc[0][2]); acc[0][3] = fmaf(a.x, b.w, acc[0][3]);
            acc[1][0] = fmaf(a.y, b.x, acc[1][0]); acc[1][1] = fmaf(a.y, b.y, acc[1][1]);
            acc[1][2] = fmaf(a.y, b.z, acc[1][2]); acc[1][3] = fmaf(a.y, b.w, acc[1][3]);
            acc[2][0] = fmaf(a.z, b.x, acc[2][0]); acc[2][1] = fmaf(a.z, b.y, acc[2][1]);
            acc[2][2] = fmaf(a.z, b.z, acc[2][2]); acc[2][3] = fmaf(a.z, b.w, acc[2][3]);
            acc[3][0] = fmaf(a.w, b.x, acc[3][0]); acc[3][1] = fmaf(a.w, b.y, acc[3][1]);
            acc[3][2] = fmaf(a.w, b.z, acc[3][2]); acc[3][3] = fmaf(a.w, b.w, acc[3][3]);
        }
        __syncthreads();
    }
    float b0 = bias[n0 + tx * 4 + 0], b1 = bias[n0 + tx * 4 + 1];
    float b2 = bias[n0 + tx * 4 + 2], b3 = bias[n0 + tx * 4 + 3];
#pragma unroll
    for (int i = 0; i < 4; i++) {
        int r = rBase + ty * 4 + i;
        int is = r >> 8, bb = r & 255;
        size_t orow = (size_t)(bb * 512 + (511 - is)) * 128;
        float4 v = make_float4(acc[i][0] + b0, acc[i][1] + b1, acc[i][2] + b2, acc[i][3] + b3);
        *(float4*)&out[OFF_OUT + orow + n0 + tx * 4] = v;
    }
}

// ---------------------------------------------------------------------------
// Fold: Mf[g][j] = sum_f dec_Wih[g,f]*out_W[f,j];  bf[g] = dec_bih[g] + dec_Wih[g,:].out_b
// ---------------------------------------------------------------------------
__global__ void fold_kernel(const float* __restrict__ dWih, const float* __restrict__ outW,
                            const float* __restrict__ outb, const float* __restrict__ dbih) {
    int g = blockIdx.x, j = threadIdx.x;
    __shared__ float wrow[128];
    __shared__ float red[128];
    wrow[j] = dWih[g * 128 + j];
    __syncthreads();
    float acc = 0.0f;
#pragma unroll 8
    for (int f = 0; f < 128; f++) acc = fmaf(wrow[f], outW[f * 128 + j], acc);
    g_Mf[g * 128 + j] = acc;
    red[j] = wrow[j] * outb[j];
    __syncthreads();
    for (int s = 64; s > 0; s >>= 1) {
        if (j < s) red[j] += red[j + s];
        __syncthreads();
    }
    if (j == 0) g_bf[g] = dbih[g] + red[0];
}

// ---------------------------------------------------------------------------
// Encoder recurrence (FFMA2 over k-pairs): 128 CTAs x 384 threads; 2 batch/CTA.
// Thread g holds Whh row g as 64 packed pairs in registers.
// ---------------------------------------------------------------------------
__global__ void __launch_bounds__(384, 1) enc_kernel(const float* __restrict__ Whh,
                                                     const float* __restrict__ bhh) {
    __shared__ __align__(16) float h_sm[2][128];
    __shared__ float gh_sm[2][384];
    int g = threadIdx.x;
    int b0 = blockIdx.x * 2;
    ull w2[64];
    {
        const ull* wrow = (const ull*)Whh + (size_t)g * 64;
#pragma unroll
        for (int kp = 0; kp < 64; kp++) w2[kp] = wrow[kp];
    }
    float bg = bhh[g];
    int bb = g >> 7, j = g & 127;
    if (g < 256) h_sm[bb][j] = 0.0f;
    __syncthreads();

    for (int t = 0; t < 512; t++) {
        float gi_r = 0.f, gi_z = 0.f, gi_n = 0.f;
        if (g < 256) {
            const float* gp = g_Genc + ((size_t)t * 256 + b0 + bb) * 384;
            gi_r = gp[j]; gi_z = gp[128 + j]; gi_n = gp[256 + j];
        }
        ull a0 = pk2(bg, 0.f), a1 = pk2(bg, 0.f);
#pragma unroll
        for (int q = 0; q < 32; q++) {
            ulonglong2 h0 = *(const ulonglong2*)&h_sm[0][4 * q];
            ulonglong2 h1 = *(const ulonglong2*)&h_sm[1][4 * q];
            a0 = f2fma(w2[2 * q],     h0.x, a0);
            a1 = f2fma(w2[2 * q],     h1.x, a1);
            a0 = f2fma(w2[2 * q + 1], h0.y, a0);
            a1 = f2fma(w2[2 * q + 1], h1.y, a1);
        }
        gh_sm[0][g] = psum(a0);
        gh_sm[1][g] = psum(a1);
        __syncthreads();
        if (g < 256) {
            float r = sigf(gi_r + gh_sm[bb][j]);
            float z = sigf(gi_z + gh_sm[bb][128 + j]);
            float n = tanhf(gi_n + r * gh_sm[bb][256 + j]);
            h_sm[bb][j] = (1.0f - z) * n + z * h_sm[bb][j];
        }
        __syncthreads();
    }
    if (g < 256) g_Henc[(b0 + bb) * 128 + j] = h_sm[bb][j];
}

// ---------------------------------------------------------------------------
// Decoder recurrence v3: BOTH weight matrices register-resident.
// Thread g holds Mf row g (w2[64]) AND dec_Whh row g (v2[64]) as packed pairs
// = 128 weight regs. No smem weight stream at all — per-step smem traffic is
// only broadcast h reads and the 4x384 gate writes. FMA-bound:
// 3 warps/SMSP x 256 FFMA2 x rt2 = 1536 cyc/step.
// ---------------------------------------------------------------------------
__global__ void __launch_bounds__(384, 1) dec_kernel(const float* __restrict__ Whh,
                                                     const float* __restrict__ bhh) {
    __shared__ __align__(16) float hsm[256];
    __shared__ float gis[768];
    __shared__ float ghs[768];
    int g = threadIdx.x;
    int b0 = blockIdx.x * 2;
    int bb = g >> 7, j = g & 127;

    ull w2[64], v2[64];
    {
        const ull* mrow = (const ull*)g_Mf + (size_t)g * 64;
        const ull* vrow = (const ull*)Whh + (size_t)g * 64;
#pragma unroll
        for (int kp = 0; kp < 64; kp++) w2[kp] = mrow[kp];
#pragma unroll
        for (int kp = 0; kp < 64; kp++) v2[kp] = vrow[kp];
    }
    float bfg = g_bf[g];
    float bhg = bhh[g];

    if (g < 256) {
        float h_init = g_Henc[b0 * 128 + g];
        hsm[g] = h_init;
        g_Hdec[((size_t)0 * 256 + b0 + bb) * 128 + j] = h_init;  // state entering step 0
    }
    __syncthreads();

    for (int i = 0; i < 512; i++) {
        ull gi0 = pk2(bfg, 0.f), gi1 = pk2(bfg, 0.f);
        ull gh0 = pk2(bhg, 0.f), gh1 = pk2(bhg, 0.f);
#pragma unroll
        for (int q = 0; q < 32; q++) {
            ulonglong2 h0 = *(const ulonglong2*)&hsm[4 * q];
            ulonglong2 h1 = *(const ulonglong2*)&hsm[128 + 4 * q];
            gi0 = f2fma(w2[2 * q],     h0.x, gi0);
            gh0 = f2fma(v2[2 * q],     h0.x, gh0);
            gi1 = f2fma(w2[2 * q],     h1.x, gi1);
            gh1 = f2fma(v2[2 * q],     h1.x, gh1);
            gi0 = f2fma(w2[2 * q + 1], h0.y, gi0);
            gh0 = f2fma(v2[2 * q + 1], h0.y, gh0);
            gi1 = f2fma(w2[2 * q + 1], h1.y, gi1);
            gh1 = f2fma(v2[2 * q + 1], h1.y, gh1);
        }
        gis[g] = psum(gi0); gis[384 + g] = psum(gi1);
        ghs[g] = psum(gh0); ghs[384 + g] = psum(gh1);
        __syncthreads();
        if (g < 256) {
            int base = bb * 384;
            float r = sigf(gis[base + j] + ghs[base + j]);
            float z = sigf(gis[base + 128 + j] + ghs[base + 128 + j]);
            float n = tanhf(gis[base + 256 + j] + r * ghs[base + 256 + j]);
            float h_new = (1.0f - z) * n + z * hsm[g];
            hsm[g] = h_new;
            if (i < 511)
                g_Hdec[((size_t)(i + 1) * 256 + b0 + bb) * 128 + j] = h_new;
        }
        __syncthreads();
    }
}

// ---------------------------------------------------------------------------
// Epilogue A: cosine, h_enc copy, LN/attn/dis/z/gamma. One block per batch elem.
// ---------------------------------------------------------------------------
__device__ __forceinline__ float bsum(float v, float* red) {
    int t = threadIdx.x;
    __syncthreads();
    red[t] = v;
    __syncthreads();
    for (int s = 128; s > 0; s >>= 1) {
        if (t < s) red[t] += red[t + s];
        __syncthreads();
    }
    return red[0];
}

__global__ void __launch_bounds__(256) epiA(
    const float* __restrict__ X,
    const float* __restrict__ protos,
    const float* __restrict__ lnzw, const float* __restrict__ lnzb,
    const float* __restrict__ lnpw, const float* __restrict__ lnpb,
    const float* __restrict__ lnaw, const float* __restrict__ lnab,
    const float* __restrict__ beta,
    const float* __restrict__ e1W, const float* __restrict__ e1b,
    const float* __restrict__ e2W, const float* __restrict__ e2b,
    float* __restrict__ out) {
    int b = blockIdx.x, t = threadIdx.x;
    __shared__ float red[256];
    __shared__ float zln[128];
    __shared__ float pl[8][128];
    __shared__ float dotk[8];
    __shared__ float attnv[8];
    __shared__ float zfull[129];
    __shared__ float h1s[10];
    __shared__ float lg[4];

    // rec_cosine
    const float* a = X + (size_t)b * 65536;
    const float* o = out + OFF_OUT + (size_t)b * 65536;
    float sab = 0.f, saa = 0.f, sbb = 0.f;
    for (int i = t; i < 65536; i += 256) {
        float av = a[i], bv = o[i];
        sab = fmaf(av, bv, sab);
        saa = fmaf(av, av, saa);
        sbb = fmaf(bv, bv, sbb);
    }
    sab = bsum(sab, red);
    saa = bsum(saa, red);
    sbb = bsum(sbb, red);
    float rc = sab / (fmaxf(sqrtf(saa), 1e-8f) * fmaxf(sqrtf(sbb), 1e-8f));

    // h_enc copy + LN(z)
    float h = (t < 128) ? g_Henc[b * 128 + t] : 0.0f;
    if (t < 128) out[OFF_HENC + b * 128 + t] = h;
    float mu = bsum(h, red) * (1.0f / 128.0f);
    float d = (t < 128) ? (h - mu) : 0.0f;
    float var = bsum(d * d, red) * (1.0f / 128.0f);
    if (t < 128) zln[t] = lnzw[t] * d * rsqrtf(var + 1e-12f) + lnzb[t];

    // LN(prototypes)
    for (int k = 0; k < 8; k++) {
        float p = (t < 128) ? protos[k * 128 + t] : 0.0f;
        float pu = bsum(p, red) * (1.0f / 128.0f);
        float pd = (t < 128) ? (p - pu) : 0.0f;
        float pv = bsum(pd * pd, red) * (1.0f / 128.0f);
        if (t < 128) pl[k][t] = lnpw[t] * pd * rsqrtf(pv + 1e-12f) + lnpb[t];
    }
    __syncthreads();

    // attn = softmax(z_ln @ prot_ln^T / sqrt(H))
    for (int k = 0; k < 8; k++) {
        float pp = (t < 128) ? zln[t] * pl[k][t] : 0.0f;
        float s = bsum(pp, red);
        if (t == 0) dotk[k] = s * 0.08838834764831845f;  // 1/sqrt(128)
    }
    __syncthreads();
    if (t < 8) {
        float m = -1e30f;
        for (int kk = 0; kk < 8; kk++) m = fmaxf(m, dotk[kk]);
        float s = 0.f;
        for (int kk = 0; kk < 8; kk++) s += expf(dotk[kk] - m);
        attnv[t] = expf(dotk[t] - m) / s;
    }
    __syncthreads();

    // dis + z mean
    float zacc = 0.0f;
    for (int k = 0; k < 8; k++) {
        float v = (t < 128) ? (beta[k * 128 + t] + attnv[k] * h) : 0.0f;
        float vu = bsum(v, red) * (1.0f / 128.0f);
        float vd = (t < 128) ? (v - vu) : 0.0f;
        float vv = bsum(vd * vd, red) * (1.0f / 128.0f);
        if (t < 128) {
            float dval = lnaw[t] * vd * rsqrtf(vv + 1e-12f) + lnab[t];
            out[OFF_DIS + ((size_t)b * 8 + k) * 128 + t] = dval;
            zacc += dval;
        }
    }
    if (t < 128) {
        float zv = zacc * 0.125f;
        zfull[t] = zv;
        out[OFF_Z + (size_t)b * 129 + t] = zv;
    }
    if (t == 0) {
        zfull[128] = rc;
        out[OFF_Z + (size_t)b * 129 + 128] = rc;
    }
    __syncthreads();

    if (t < 10) {
        float acc = e1b[t];
        for (int i = 0; i < 129; i++) acc = fmaf(e1W[t * 129 + i], zfull[i], acc);
        h1s[t] = tanhf(acc);
    }
    __syncthreads();
    if (t < 4) {
        float acc = e2b[t];
        for (int i = 0; i < 10; i++) acc = fmaf(e2W[t * 10 + i], h1s[i], acc);
        lg[t] = acc;
    }
    __syncthreads();
    if (t < 4) {
        float m = fmaxf(fmaxf(lg[0], lg[1]), fmaxf(lg[2], lg[3]));
        float s = expf(lg[0] - m) + expf(lg[1] - m) + expf(lg[2] - m) + expf(lg[3] - m);
        out[OFF_GAMMA + (size_t)b * 4 + t] = expf(lg[t] - m) / s;
    }
}

// dis_perm[b,k,:] = dis[perm_k[b], k, :]
__global__ void epiB(float* __restrict__ out, const int* __restrict__ perm) {
    int b = blockIdx.x;
    for (int e = threadIdx.x; e < 1024; e += blockDim.x) {
        int k = e >> 7, j = e & 127;
        int src = perm[k * 256 + b];
        out[OFF_DISP + ((size_t)b * 8 + k) * 128 + j] =
            out[OFF_DIS + ((size_t)src * 8 + k) * 128 + j];
    }
}

// ---------------------------------------------------------------------------
extern "C" void kernel_launch(void* const* d_in, const int* in_sizes, int n_in,
                              void* d_out, int out_size) {
    const float* input   = (const float*)d_in[0];
    const float* enc_Wih = (const float*)d_in[1];
    const float* enc_Whh = (const float*)d_in[2];
    const float* enc_bih = (const float*)d_in[3];
    const float* enc_bhh = (const float*)d_in[4];
    const float* dec_Wih = (const float*)d_in[5];
    const float* dec_Whh = (const float*)d_in[6];
    const float* dec_bih = (const float*)d_in[7];
    const float* dec_bhh = (const float*)d_in[8];
    const float* out_W   = (const float*)d_in[9];
    const float* out_b   = (const float*)d_in[10];
    const float* protos  = (const float*)d_in[11];
    const float* lnz_w   = (const float*)d_in[12];
    const float* lnz_b   = (const float*)d_in[13];
    const float* lnp_w   = (const float*)d_in[14];
    const float* lnp_b   = (const float*)d_in[15];
    const float* lna_w   = (const float*)d_in[16];
    const float* lna_b   = (const float*)d_in[17];
    const float* beta    = (const float*)d_in[18];
    const float* est1_W  = (const float*)d_in[19];
    const float* est1_b  = (const float*)d_in[20];
    const float* est2_W  = (const float*)d_in[21];
    const float* est2_b  = (const float*)d_in[22];
    float* out = (float*)d_out;

    int* perm_ptr = nullptr;
    cudaGetSymbolAddress((void**)&perm_ptr, g_perm);

    // 1. Encoder input gates (time-parallel GEMM)
    gemm_gi<<<dim3(2048, 6), 256>>>(input, enc_Wih, enc_bih);
    // 2. Encoder recurrence (FFMA2, register weights)
    enc_kernel<<<128, 384>>>(enc_Whh, enc_bhh);
    // 3. Fold output projection into decoder input weights
    fold_kernel<<<384, 128>>>(dec_Wih, out_W, out_b, dec_bih);
    // 4. Decoder recurrence (FFMA2, BOTH weights in registers)
    dec_kernel<<<128, 384>>>(dec_Whh, dec_bhh);
    // 5. Output projection for all 512 steps (parallel GEMM)
    gemm_out<<<dim3(2048, 2), 256>>>(out_W, out_b, out);
    // 6. JAX-exact permutations (threefry_partitionable scheme)
    perm_kernel<<<1, 256>>>(perm_ptr);
    // 7. Epilogue: cosine, LN, attention, dis, z, gamma
    epiA<<<256, 256>>>(input, protos, lnz_w, lnz_b, lnp_w, lnp_b, lna_w, lna_b,
                       beta, est1_W, est1_b, est2_W, est2_b, out);
    // 8. dis_perm gather
    epiB<<<256, 256>>>(out, perm_ptr);
}

// round 9
// speedup vs baseline: 2.0560x; 2.0560x over previous
#include <cuda_runtime.h>
#include <cuda_bf16.h>
#include <math.h>
#include <stdint.h>
#include <stddef.h>

// Problem dims
#define Bsz 256
#define Ssz 512
#define Fdim 128
#define Hdim 128
#define G3  384   // 3*H

// Output layout (tuple flattened): h_enc, output, z, gamma, dis, dis_perm
#define OFF_HENC  ((size_t)0)
#define OFF_OUT   ((size_t)32768)                       // 256*128
#define OFF_Z     ((size_t)(32768 + 16777216))          // + 256*512*128
#define OFF_GAMMA ((size_t)(OFF_Z + 256*129))
#define OFF_DIS   ((size_t)(OFF_GAMMA + 256*4))
#define OFF_DISP  ((size_t)(OFF_DIS + 256*8*128))

typedef unsigned long long ull;

// Scratch (device globals; no allocations allowed)
__device__ float g_Genc[(size_t)Ssz * Bsz * G3];    // [t][b][g]  192 MB
__device__ float g_Hdec[(size_t)Ssz * Bsz * Hdim];  // [i][b][j]   64 MB
__device__ float g_Henc[Bsz * Hdim];
__device__ float g_Mf[G3 * Hdim];
__device__ float g_bf[G3];
__device__ int   g_perm[8 * Bsz];                   // [k][pos] -> batch idx

__device__ __forceinline__ float sigf(float x) { return 1.0f / (1.0f + expf(-x)); }

// ---- packed f32x2 helpers ----
__device__ __forceinline__ ull pk2(float lo, float hi) {
    ull r; asm("mov.b64 %0, {%1, %2};" : "=l"(r) : "f"(lo), "f"(hi)); return r;
}
__device__ __forceinline__ ull f2fma(ull a, ull b, ull c) {
    ull d; asm("fma.rn.f32x2 %0, %1, %2, %3;" : "=l"(d) : "l"(a), "l"(b), "l"(c)); return d;
}
__device__ __forceinline__ float psum(ull v) {
    float a, b; asm("mov.b64 {%0, %1}, %2;" : "=f"(a), "=f"(b) : "l"(v)); return a + b;
}

// ---------------------------------------------------------------------------
// Threefry2x32 core (20 rounds, exact JAX constants)
// ---------------------------------------------------------------------------
__device__ __forceinline__ uint2 threefry(unsigned k0, unsigned k1,
                                          unsigned x0, unsigned x1) {
    unsigned ks2 = k0 ^ k1 ^ 0x1BD11BDAu;
    x0 += k0; x1 += k1;
#define TFR(r) { x0 += x1; x1 = (x1 << (r)) | (x1 >> (32 - (r))); x1 ^= x0; }
    TFR(13) TFR(15) TFR(26) TFR(6)   x0 += k1;  x1 += ks2 + 1u;
    TFR(17) TFR(29) TFR(16) TFR(24)  x0 += ks2; x1 += k0 + 2u;
    TFR(13) TFR(15) TFR(26) TFR(6)   x0 += k0;  x1 += k1 + 3u;
    TFR(17) TFR(29) TFR(16) TFR(24)  x0 += k1;  x1 += ks2 + 4u;
    TFR(13) TFR(15) TFR(26) TFR(6)   x0 += ks2; x1 += k0 + 5u;
#undef TFR
    return make_uint2(x0, x1);
}

// JAX threefry_partitionable=True reproduction (verified passing since R5)
__global__ void perm_kernel(int* __restrict__ perm) {
    __shared__ unsigned sk[8][2];
    __shared__ unsigned bits[256];
    int t = threadIdx.x;
    if (t < 8) {
        uint2 pk = threefry(0u, 42u, 0u, (unsigned)t);
        uint2 s  = threefry(pk.x, pk.y, 0u, 1u);
        sk[t][0] = s.x; sk[t][1] = s.y;
    }
    __syncthreads();
    for (int k = 0; k < 8; k++) {
        uint2 y = threefry(sk[k][0], sk[k][1], 0u, (unsigned)t);
        bits[t] = y.x ^ y.y;
        __syncthreads();
        unsigned mine = bits[t];
        int rank = 0;
        for (int j = 0; j < 256; j++) {
            unsigned o = bits[j];
            rank += (o < mine) || (o == mine && j < t);
        }
        perm[k * 256 + rank] = t;
        __syncthreads();
    }
}

// ---------------------------------------------------------------------------
// GEMM A (R5-exact math; grid axes SWAPPED so consecutive CTAs share the row
// tile -> X read once from HBM, 6 column-passes hit L2):
// g_Genc[r][g] = x . enc_Wih[g,:] + bias.  Launch dim3(6, 2048).
// ---------------------------------------------------------------------------
__global__ void __launch_bounds__(256) gemm_gi(const float* __restrict__ X,
                                               const float* __restrict__ W,
                                               const float* __restrict__ bias) {
    __shared__ float As[32 * 64];
    __shared__ float Bs[32 * 64];
    int tid = threadIdx.x;
    int tx = tid & 15, ty = tid >> 4;
    int rBase = blockIdx.y * 64;   // row tile (slow axis)
    int n0 = blockIdx.x * 64;      // col tile (fast axis -> L2 reuse of X)
    float acc[4][4];
#pragma unroll
    for (int i = 0; i < 4; i++)
#pragma unroll
        for (int j = 0; j < 4; j++) acc[i][j] = 0.0f;

    for (int kc = 0; kc < 4; kc++) {
        int k0 = kc * 32;
#pragma unroll
        for (int p = 0; p < 2; p++) {
            int l = tid + p * 256;
            int row = l >> 3, q = l & 7;
            int r = rBase + row;
            const float* xp = X + (((size_t)(r & 255) * 512 + (r >> 8)) << 7);
            float4 v = *(const float4*)&xp[k0 + q * 4];
            As[(q * 4 + 0) * 64 + row] = v.x;
            As[(q * 4 + 1) * 64 + row] = v.y;
            As[(q * 4 + 2) * 64 + row] = v.z;
            As[(q * 4 + 3) * 64 + row] = v.w;
        }
#pragma unroll
        for (int p = 0; p < 2; p++) {
            int l = tid + p * 256;
            int n = l >> 3, q = l & 7;
            float4 v = *(const float4*)&W[(size_t)(n0 + n) * 128 + k0 + q * 4];
            Bs[(q * 4 + 0) * 64 + n] = v.x;
            Bs[(q * 4 + 1) * 64 + n] = v.y;
            Bs[(q * 4 + 2) * 64 + n] = v.z;
            Bs[(q * 4 + 3) * 64 + n] = v.w;
        }
        __syncthreads();
#pragma unroll
        for (int kk = 0; kk < 32; kk++) {
            float4 a = *(const float4*)&As[kk * 64 + ty * 4];
            float4 b = *(const float4*)&Bs[kk * 64 + tx * 4];
            acc[0][0] = fmaf(a.x, b.x, acc[0][0]); acc[0][1] = fmaf(a.x, b.y, acc[0][1]);
            acc[0][2] = fmaf(a.x, b.z, acc[0][2]); acc[0][3] = fmaf(a.x, b.w, acc[0][3]);
            acc[1][0] = fmaf(a.y, b.x, acc[1][0]); acc[1][1] = fmaf(a.y, b.y, acc[1][1]);
            acc[1][2] = fmaf(a.y, b.z, acc[1][2]); acc[1][3] = fmaf(a.y, b.w, acc[1][3]);
            acc[2][0] = fmaf(a.z, b.x, acc[2][0]); acc[2][1] = fmaf(a.z, b.y, acc[2][1]);
            acc[2][2] = fmaf(a.z, b.z, acc[2][2]); acc[2][3] = fmaf(a.z, b.w, acc[2][3]);
            acc[3][0] = fmaf(a.w, b.x, acc[3][0]); acc[3][1] = fmaf(a.w, b.y, acc[3][1]);
            acc[3][2] = fmaf(a.w, b.z, acc[3][2]); acc[3][3] = fmaf(a.w, b.w, acc[3][3]);
        }
        __syncthreads();
    }
    float b0 = bias[n0 + tx * 4 + 0], b1 = bias[n0 + tx * 4 + 1];
    float b2 = bias[n0 + tx * 4 + 2], b3 = bias[n0 + tx * 4 + 3];
#pragma unroll
    for (int i = 0; i < 4; i++) {
        int r = rBase + ty * 4 + i;
        float4 v = make_float4(acc[i][0] + b0, acc[i][1] + b1, acc[i][2] + b2, acc[i][3] + b3);
        *(float4*)&g_Genc[(size_t)r * 384 + n0 + tx * 4] = v;
    }
}

// ---------------------------------------------------------------------------
// out-GEMM (R5-exact math; grid swapped): o_i = Hdec[i] @ out_W^T + out_b.
// Launch dim3(2, 2048).
// ---------------------------------------------------------------------------
__global__ void __launch_bounds__(256) gemm_out(const float* __restrict__ W,
                                                const float* __restrict__ bias,
                                                float* __restrict__ out) {
    __shared__ float As[32 * 64];
    __shared__ float Bs[32 * 64];
    int tid = threadIdx.x;
    int tx = tid & 15, ty = tid >> 4;
    int rBase = blockIdx.y * 64;
    int n0 = blockIdx.x * 64;
    float acc[4][4];
#pragma unroll
    for (int i = 0; i < 4; i++)
#pragma unroll
        for (int j = 0; j < 4; j++) acc[i][j] = 0.0f;

    for (int kc = 0; kc < 4; kc++) {
        int k0 = kc * 32;
#pragma unroll
        for (int p = 0; p < 2; p++) {
            int l = tid + p * 256;
            int row = l >> 3, q = l & 7;
            int r = rBase + row;
            float4 v = *(const float4*)&g_Hdec[(size_t)r * 128 + k0 + q * 4];
            As[(q * 4 + 0) * 64 + row] = v.x;
            As[(q * 4 + 1) * 64 + row] = v.y;
            As[(q * 4 + 2) * 64 + row] = v.z;
            As[(q * 4 + 3) * 64 + row] = v.w;
        }
#pragma unroll
        for (int p = 0; p < 2; p++) {
            int l = tid + p * 256;
            int n = l >> 3, q = l & 7;
            float4 v = *(const float4*)&W[(size_t)(n0 + n) * 128 + k0 + q * 4];
            Bs[(q * 4 + 0) * 64 + n] = v.x;
            Bs[(q * 4 + 1) * 64 + n] = v.y;
            Bs[(q * 4 + 2) * 64 + n] = v.z;
            Bs[(q * 4 + 3) * 64 + n] = v.w;
        }
        __syncthreads();
#pragma unroll
        for (int kk = 0; kk < 32; kk++) {
            float4 a = *(const float4*)&As[kk * 64 + ty * 4];
            float4 b = *(const float4*)&Bs[kk * 64 + tx * 4];
            acc[0][0] = fmaf(a.x, b.x, acc[0][0]); acc[0][1] = fmaf(a.x, b.y, acc[0][1]);
            acc[0][2] = fmaf(a.x, b.z, acc[0][2]); acc[0][3] = fmaf(a.x, b.w, acc[0][3]);
            acc[1][0] = fmaf(a.y, b.x, acc[1][0]); acc[1][1] = fmaf(a.y, b.y, acc[1][1]);
            acc[1][2] = fmaf(a.y, b.z, acc[1][2]); acc[1][3] = fmaf(a.y, b.w, acc[1][3]);
            acc[2][0] = fmaf(a.z, b.x, acc[2][0]); acc[2][1] = fmaf(a.z, b.y, acc[2][1]);
            acc[2][2] = fmaf(a.z, b.z, acc[2][2]); acc[2][3] = fmaf(a.z, b.w, acc[2][3]);
            acc[3][0] = fmaf(a.w, b.x, acc[3][0]); acc[3][1] = fmaf(a.w, b.y, acc[3][1]);
            acc[3][2] = fmaf(a.w, b.z, acc[3][2]); acc[3][3] = fmaf(a.w, b.w, acc[3][3]);
        }
        __syncthreads();
    }
    float b0 = bias[n0 + tx * 4 + 0], b1 = bias[n0 + tx * 4 + 1];
    float b2 = bias[n0 + tx * 4 + 2], b3 = bias[n0 + tx * 4 + 3];
#pragma unroll
    for (int i = 0; i < 4; i++) {
        int r = rBase + ty * 4 + i;
        int is = r >> 8, bb = r & 255;
        size_t orow = (size_t)(bb * 512 + (511 - is)) * 128;
        float4 v = make_float4(acc[i][0] + b0, acc[i][1] + b1, acc[i][2] + b2, acc[i][3] + b3);
        *(float4*)&out[OFF_OUT + orow + n0 + tx * 4] = v;
    }
}

// ---------------------------------------------------------------------------
// Fold: Mf[g][j] = sum_f dec_Wih[g,f]*out_W[f,j];  bf[g] = dec_bih[g] + dec_Wih[g,:].out_b
// ---------------------------------------------------------------------------
__global__ void fold_kernel(const float* __restrict__ dWih, const float* __restrict__ outW,
                            const float* __restrict__ outb, const float* __restrict__ dbih) {
    int g = blockIdx.x, j = threadIdx.x;
    __shared__ float wrow[128];
    __shared__ float red[128];
    wrow[j] = dWih[g * 128 + j];
    __syncthreads();
    float acc = 0.0f;
#pragma unroll 8
    for (int f = 0; f < 128; f++) acc = fmaf(wrow[f], outW[f * 128 + j], acc);
    g_Mf[g * 128 + j] = acc;
    red[j] = wrow[j] * outb[j];
    __syncthreads();
    for (int s = 64; s > 0; s >>= 1) {
        if (j < s) red[j] += red[j + s];
        __syncthreads();
    }
    if (j == 0) g_bf[g] = dbih[g] + red[0];
}

// ---------------------------------------------------------------------------
// Encoder recurrence (FFMA2): 128 CTAs x 384 threads; 2 batch/CTA.
// Thread g holds Whh row g as 64 packed pairs (128 regs).
// ---------------------------------------------------------------------------
__global__ void __launch_bounds__(384, 1) enc_kernel(const float* __restrict__ Whh,
                                                     const float* __restrict__ bhh) {
    __shared__ __align__(16) float h_sm[2][128];
    __shared__ float gh_sm[2][384];
    int g = threadIdx.x;
    int b0 = blockIdx.x * 2;
    ull w2[64];
    {
        const ull* wrow = (const ull*)Whh + (size_t)g * 64;
#pragma unroll
        for (int kp = 0; kp < 64; kp++) w2[kp] = wrow[kp];
    }
    float bg = bhh[g];
    int bb = g >> 7, j = g & 127;
    if (g < 256) h_sm[bb][j] = 0.0f;
    __syncthreads();

    for (int t = 0; t < 512; t++) {
        float gi_r = 0.f, gi_z = 0.f, gi_n = 0.f;
        if (g < 256) {
            const float* gp = g_Genc + ((size_t)t * 256 + b0 + bb) * 384;
            gi_r = gp[j]; gi_z = gp[128 + j]; gi_n = gp[256 + j];
        }
        ull a0 = pk2(bg, 0.f), a1 = pk2(bg, 0.f);
#pragma unroll
        for (int q = 0; q < 32; q++) {
            ulonglong2 h0 = *(const ulonglong2*)&h_sm[0][4 * q];
            ulonglong2 h1 = *(const ulonglong2*)&h_sm[1][4 * q];
            a0 = f2fma(w2[2 * q],     h0.x, a0);
            a1 = f2fma(w2[2 * q],     h1.x, a1);
            a0 = f2fma(w2[2 * q + 1], h0.y, a0);
            a1 = f2fma(w2[2 * q + 1], h1.y, a1);
        }
        gh_sm[0][g] = psum(a0);
        gh_sm[1][g] = psum(a1);
        __syncthreads();
        if (g < 256) {
            float r = sigf(gi_r + gh_sm[bb][j]);
            float z = sigf(gi_z + gh_sm[bb][128 + j]);
            float n = tanhf(gi_n + r * gh_sm[bb][256 + j]);
            h_sm[bb][j] = (1.0f - z) * n + z * h_sm[bb][j];
        }
        __syncthreads();
    }
    if (g < 256) g_Henc[(b0 + bb) * 128 + j] = h_sm[bb][j];
}

// ---------------------------------------------------------------------------
// Decoder recurrence (R7-exact, best measured 955.8us). Mf in regs (128),
// dec_Whh streamed from smem as ulonglong2 wq[32][384]; grouped loads/gi/gh.
// ---------------------------------------------------------------------------
__global__ void __launch_bounds__(384, 1) dec_kernel(const float* __restrict__ Whh,
                                                     const float* __restrict__ bhh) {
    extern __shared__ __align__(16) unsigned char dsm[];
    ulonglong2* wq = (ulonglong2*)dsm;                 // [32][384] -> 196608 B
    float* hsm = (float*)(dsm + 196608);               // [2][128]
    float* gis = hsm + 256;                            // [2][384]
    float* ghs = gis + 768;                            // [2][384]
    int g = threadIdx.x;
    int b0 = blockIdx.x * 2;
    int bb = g >> 7, j = g & 127;

    ull w2[64];
    {
        const ull* wrow = (const ull*)g_Mf + (size_t)g * 64;
#pragma unroll
        for (int kp = 0; kp < 64; kp++) w2[kp] = wrow[kp];
    }
    float bfg = g_bf[g];
    float bhg = bhh[g];

    for (int idx = g; idx < 384 * 32; idx += 384) {
        int gg = idx >> 5, q = idx & 31;
        wq[q * 384 + gg] = ((const ulonglong2*)Whh)[(size_t)gg * 32 + q];
    }
    if (g < 256) {
        float h_init = g_Henc[b0 * 128 + g];
        hsm[g] = h_init;
        g_Hdec[((size_t)0 * 256 + b0 + bb) * 128 + j] = h_init;
    }
    __syncthreads();

    for (int i = 0; i < 512; i++) {
        ull gi0 = pk2(bfg, 0.f), gi1 = pk2(bfg, 0.f);
        ull gh0 = pk2(bhg, 0.f), gh1 = pk2(bhg, 0.f);
#pragma unroll
        for (int grp = 0; grp < 16; grp++) {
            ulonglong2 wvA = wq[(2 * grp) * 384 + g];
            ulonglong2 wvB = wq[(2 * grp + 1) * 384 + g];
            ulonglong2 h0A = *(const ulonglong2*)&hsm[8 * grp];
            ulonglong2 h0B = *(const ulonglong2*)&hsm[8 * grp + 4];
            ulonglong2 h1A = *(const ulonglong2*)&hsm[128 + 8 * grp];
            ulonglong2 h1B = *(const ulonglong2*)&hsm[128 + 8 * grp + 4];
            gi0 = f2fma(w2[4 * grp],     h0A.x, gi0);
            gi1 = f2fma(w2[4 * grp],     h1A.x, gi1);
            gi0 = f2fma(w2[4 * grp + 1], h0A.y, gi0);
            gi1 = f2fma(w2[4 * grp + 1], h1A.y, gi1);
            gi0 = f2fma(w2[4 * grp + 2], h0B.x, gi0);
            gi1 = f2fma(w2[4 * grp + 2], h1B.x, gi1);
            gi0 = f2fma(w2[4 * grp + 3], h0B.y, gi0);
            gi1 = f2fma(w2[4 * grp + 3], h1B.y, gi1);
            gh0 = f2fma(wvA.x, h0A.x, gh0);
            gh1 = f2fma(wvA.x, h1A.x, gh1);
            gh0 = f2fma(wvA.y, h0A.y, gh0);
            gh1 = f2fma(wvA.y, h1A.y, gh1);
            gh0 = f2fma(wvB.x, h0B.x, gh0);
            gh1 = f2fma(wvB.x, h1B.x, gh1);
            gh0 = f2fma(wvB.y, h0B.y, gh0);
            gh1 = f2fma(wvB.y, h1B.y, gh1);
        }
        gis[g] = psum(gi0); gis[384 + g] = psum(gi1);
        ghs[g] = psum(gh0); ghs[384 + g] = psum(gh1);
        __syncthreads();
        if (g < 256) {
            int base = bb * 384;
            float r = sigf(gis[base + j] + ghs[base + j]);
            float z = sigf(gis[base + 128 + j] + ghs[base + 128 + j]);
            float n = tanhf(gis[base + 256 + j] + r * ghs[base + 256 + j]);
            float h_new = (1.0f - z) * n + z * hsm[g];
            hsm[g] = h_new;
            if (i < 511)
                g_Hdec[((size_t)(i + 1) * 256 + b0 + bb) * 128 + j] = h_new;
        }
        __syncthreads();
    }
}

// ---------------------------------------------------------------------------
// Epilogue A: cosine, h_enc copy, LN/attn/dis/z/gamma. One block per batch elem.
// ---------------------------------------------------------------------------
__device__ __forceinline__ float bsum(float v, float* red) {
    int t = threadIdx.x;
    __syncthreads();
    red[t] = v;
    __syncthreads();
    for (int s = 128; s > 0; s >>= 1) {
        if (t < s) red[t] += red[t + s];
        __syncthreads();
    }
    return red[0];
}

__global__ void __launch_bounds__(256) epiA(
    const float* __restrict__ X,
    const float* __restrict__ protos,
    const float* __restrict__ lnzw, const float* __restrict__ lnzb,
    const float* __restrict__ lnpw, const float* __restrict__ lnpb,
    const float* __restrict__ lnaw, const float* __restrict__ lnab,
    const float* __restrict__ beta,
    const float* __restrict__ e1W, const float* __restrict__ e1b,
    const float* __restrict__ e2W, const float* __restrict__ e2b,
    float* __restrict__ out) {
    int b = blockIdx.x, t = threadIdx.x;
    __shared__ float red[256];
    __shared__ float zln[128];
    __shared__ float pl[8][128];
    __shared__ float dotk[8];
    __shared__ float attnv[8];
    __shared__ float zfull[129];
    __shared__ float h1s[10];
    __shared__ float lg[4];

    const float* a = X + (size_t)b * 65536;
    const float* o = out + OFF_OUT + (size_t)b * 65536;
    float sab = 0.f, saa = 0.f, sbb = 0.f;
    for (int i = t; i < 65536; i += 256) {
        float av = a[i], bv = o[i];
        sab = fmaf(av, bv, sab);
        saa = fmaf(av, av, saa);
        sbb = fmaf(bv, bv, sbb);
    }
    sab = bsum(sab, red);
    saa = bsum(saa, red);
    sbb = bsum(sbb, red);
    float rc = sab / (fmaxf(sqrtf(saa), 1e-8f) * fmaxf(sqrtf(sbb), 1e-8f));

    float h = (t < 128) ? g_Henc[b * 128 + t] : 0.0f;
    if (t < 128) out[OFF_HENC + b * 128 + t] = h;
    float mu = bsum(h, red) * (1.0f / 128.0f);
    float d = (t < 128) ? (h - mu) : 0.0f;
    float var = bsum(d * d, red) * (1.0f / 128.0f);
    if (t < 128) zln[t] = lnzw[t] * d * rsqrtf(var + 1e-12f) + lnzb[t];

    for (int k = 0; k < 8; k++) {
        float p = (t < 128) ? protos[k * 128 + t] : 0.0f;
        float pu = bsum(p, red) * (1.0f / 128.0f);
        float pd = (t < 128) ? (p - pu) : 0.0f;
        float pv = bsum(pd * pd, red) * (1.0f / 128.0f);
        if (t < 128) pl[k][t] = lnpw[t] * pd * rsqrtf(pv + 1e-12f) + lnpb[t];
    }
    __syncthreads();

    for (int k = 0; k < 8; k++) {
        float pp = (t < 128) ? zln[t] * pl[k][t] : 0.0f;
        float s = bsum(pp, red);
        if (t == 0) dotk[k] = s * 0.08838834764831845f;
    }
    __syncthreads();
    if (t < 8) {
        float m = -1e30f;
        for (int kk = 0; kk < 8; kk++) m = fmaxf(m, dotk[kk]);
        float s = 0.f;
        for (int kk = 0; kk < 8; kk++) s += expf(dotk[kk] - m);
        attnv[t] = expf(dotk[t] - m) / s;
    }
    __syncthreads();

    float zacc = 0.0f;
    for (int k = 0; k < 8; k++) {
        float v = (t < 128) ? (beta[k * 128 + t] + attnv[k] * h) : 0.0f;
        float vu = bsum(v, red) * (1.0f / 128.0f);
        float vd = (t < 128) ? (v - vu) : 0.0f;
        float vv = bsum(vd * vd, red) * (1.0f / 128.0f);
        if (t < 128) {
            float dval = lnaw[t] * vd * rsqrtf(vv + 1e-12f) + lnab[t];
            out[OFF_DIS + ((size_t)b * 8 + k) * 128 + t] = dval;
            zacc += dval;
        }
    }
    if (t < 128) {
        float zv = zacc * 0.125f;
        zfull[t] = zv;
        out[OFF_Z + (size_t)b * 129 + t] = zv;
    }
    if (t == 0) {
        zfull[128] = rc;
        out[OFF_Z + (size_t)b * 129 + 128] = rc;
    }
    __syncthreads();

    if (t < 10) {
        float acc = e1b[t];
        for (int i = 0; i < 129; i++) acc = fmaf(e1W[t * 129 + i], zfull[i], acc);
        h1s[t] = tanhf(acc);
    }
    __syncthreads();
    if (t < 4) {
        float acc = e2b[t];
        for (int i = 0; i < 10; i++) acc = fmaf(e2W[t * 10 + i], h1s[i], acc);
        lg[t] = acc;
    }
    __syncthreads();
    if (t < 4) {
        float m = fmaxf(fmaxf(lg[0], lg[1]), fmaxf(lg[2], lg[3]));
        float s = expf(lg[0] - m) + expf(lg[1] - m) + expf(lg[2] - m) + expf(lg[3] - m);
        out[OFF_GAMMA + (size_t)b * 4 + t] = expf(lg[t] - m) / s;
    }
}

// dis_perm[b,k,:] = dis[perm_k[b], k, :]
__global__ void epiB(float* __restrict__ out, const int* __restrict__ perm) {
    int b = blockIdx.x;
    for (int e = threadIdx.x; e < 1024; e += blockDim.x) {
        int k = e >> 7, j = e & 127;
        int src = perm[k * 256 + b];
        out[OFF_DISP + ((size_t)b * 8 + k) * 128 + j] =
            out[OFF_DIS + ((size_t)src * 8 + k) * 128 + j];
    }
}

// ---------------------------------------------------------------------------
extern "C" void kernel_launch(void* const* d_in, const int* in_sizes, int n_in,
                              void* d_out, int out_size) {
    const float* input   = (const float*)d_in[0];
    const float* enc_Wih = (const float*)d_in[1];
    const float* enc_Whh = (const float*)d_in[2];
    const float* enc_bih = (const float*)d_in[3];
    const float* enc_bhh = (const float*)d_in[4];
    const float* dec_Wih = (const float*)d_in[5];
    const float* dec_Whh = (const float*)d_in[6];
    const float* dec_bih = (const float*)d_in[7];
    const float* dec_bhh = (const float*)d_in[8];
    const float* out_W   = (const float*)d_in[9];
    const float* out_b   = (const float*)d_in[10];
    const float* protos  = (const float*)d_in[11];
    const float* lnz_w   = (const float*)d_in[12];
    const float* lnz_b   = (const float*)d_in[13];
    const float* lnp_w   = (const float*)d_in[14];
    const float* lnp_b   = (const float*)d_in[15];
    const float* lna_w   = (const float*)d_in[16];
    const float* lna_b   = (const float*)d_in[17];
    const float* beta    = (const float*)d_in[18];
    const float* est1_W  = (const float*)d_in[19];
    const float* est1_b  = (const float*)d_in[20];
    const float* est2_W  = (const float*)d_in[21];
    const float* est2_b  = (const float*)d_in[22];
    float* out = (float*)d_out;

    int* perm_ptr = nullptr;
    cudaGetSymbolAddress((void**)&perm_ptr, g_perm);

    cudaFuncSetAttribute(dec_kernel, cudaFuncAttributeMaxDynamicSharedMemorySize, 204288);

    // 1. Encoder input gates (time-parallel GEMM; column axis fastest for L2 reuse)
    gemm_gi<<<dim3(6, 2048), 256>>>(input, enc_Wih, enc_bih);
    // 2. Encoder recurrence (FFMA2, register weights)
    enc_kernel<<<128, 384>>>(enc_Whh, enc_bhh);
    // 3. Fold output projection into decoder input weights
    fold_kernel<<<384, 128>>>(dec_Wih, out_W, out_b, dec_bih);
    // 4. Decoder recurrence (R7 best: Mf regs + Whh smem stream)
    dec_kernel<<<128, 384, 204288>>>(dec_Whh, dec_bhh);
    // 5. Output projection for all 512 steps (parallel GEMM)
    gemm_out<<<dim3(2, 2048), 256>>>(out_W, out_b, out);
    // 6. JAX-exact permutations
    perm_kernel<<<1, 256>>>(perm_ptr);
    // 7. Epilogue: cosine, LN, attention, dis, z, gamma
    epiA<<<256, 256>>>(input, protos, lnz_w, lnz_b, lnp_w, lnp_b, lna_w, lna_b,
                       beta, est1_W, est1_b, est2_W, est2_b, out);
    // 8. dis_perm gather
    epiB<<<256, 256>>>(out, perm_ptr);
}

// round 10
// speedup vs baseline: 2.1761x; 1.0584x over previous
#include <cuda_runtime.h>
#include <cuda_bf16.h>
#include <math.h>
#include <stdint.h>
#include <stddef.h>

// Problem dims
#define Bsz 256
#define Ssz 512
#define Fdim 128
#define Hdim 128
#define G3  384   // 3*H

// Output layout (tuple flattened): h_enc, output, z, gamma, dis, dis_perm
#define OFF_HENC  ((size_t)0)
#define OFF_OUT   ((size_t)32768)                       // 256*128
#define OFF_Z     ((size_t)(32768 + 16777216))          // + 256*512*128
#define OFF_GAMMA ((size_t)(OFF_Z + 256*129))
#define OFF_DIS   ((size_t)(OFF_GAMMA + 256*4))
#define OFF_DISP  ((size_t)(OFF_DIS + 256*8*128))

typedef unsigned long long ull;

// Scratch (device globals; no allocations allowed)
__device__ float g_Genc[(size_t)Ssz * Bsz * G3];    // [t][b][g]  192 MB
__device__ float g_Hdec[(size_t)Ssz * Bsz * Hdim];  // [i][b][j]   64 MB
__device__ float g_Henc[Bsz * Hdim];
__device__ float g_Mf[G3 * Hdim];
__device__ float g_bf[G3];
__device__ int   g_perm[8 * Bsz];                   // [k][pos] -> batch idx

__device__ __forceinline__ float sigf(float x) { return 1.0f / (1.0f + expf(-x)); }

// ---- packed f32x2 helpers (used by dec only) ----
__device__ __forceinline__ ull pk2(float lo, float hi) {
    ull r; asm("mov.b64 %0, {%1, %2};" : "=l"(r) : "f"(lo), "f"(hi)); return r;
}
__device__ __forceinline__ ull f2fma(ull a, ull b, ull c) {
    ull d; asm("fma.rn.f32x2 %0, %1, %2, %3;" : "=l"(d) : "l"(a), "l"(b), "l"(c)); return d;
}
__device__ __forceinline__ float psum(ull v) {
    float a, b; asm("mov.b64 {%0, %1}, %2;" : "=f"(a), "=f"(b) : "l"(v)); return a + b;
}

// ---------------------------------------------------------------------------
// Threefry2x32 core (20 rounds, exact JAX constants)
// ---------------------------------------------------------------------------
__device__ __forceinline__ uint2 threefry(unsigned k0, unsigned k1,
                                          unsigned x0, unsigned x1) {
    unsigned ks2 = k0 ^ k1 ^ 0x1BD11BDAu;
    x0 += k0; x1 += k1;
#define TFR(r) { x0 += x1; x1 = (x1 << (r)) | (x1 >> (32 - (r))); x1 ^= x0; }
    TFR(13) TFR(15) TFR(26) TFR(6)   x0 += k1;  x1 += ks2 + 1u;
    TFR(17) TFR(29) TFR(16) TFR(24)  x0 += ks2; x1 += k0 + 2u;
    TFR(13) TFR(15) TFR(26) TFR(6)   x0 += k0;  x1 += k1 + 3u;
    TFR(17) TFR(29) TFR(16) TFR(24)  x0 += k1;  x1 += ks2 + 4u;
    TFR(13) TFR(15) TFR(26) TFR(6)   x0 += ks2; x1 += k0 + 5u;
#undef TFR
    return make_uint2(x0, x1);
}

// JAX threefry_partitionable=True reproduction (verified passing since R5)
__global__ void perm_kernel(int* __restrict__ perm) {
    __shared__ unsigned sk[8][2];
    __shared__ unsigned bits[256];
    int t = threadIdx.x;
    if (t < 8) {
        uint2 pk = threefry(0u, 42u, 0u, (unsigned)t);
        uint2 s  = threefry(pk.x, pk.y, 0u, 1u);
        sk[t][0] = s.x; sk[t][1] = s.y;
    }
    __syncthreads();
    for (int k = 0; k < 8; k++) {
        uint2 y = threefry(sk[k][0], sk[k][1], 0u, (unsigned)t);
        bits[t] = y.x ^ y.y;
        __syncthreads();
        unsigned mine = bits[t];
        int rank = 0;
        for (int j = 0; j < 256; j++) {
            unsigned o = bits[j];
            rank += (o < mine) || (o == mine && j < t);
        }
        perm[k * 256 + rank] = t;
        __syncthreads();
    }
}

// ---------------------------------------------------------------------------
// GEMM A (R5-exact): g_Genc[t*256+b][g] = x[b,t,:] . enc_Wih[g,:] + enc_bih[g]
// Launch dim3(2048, 6).
// ---------------------------------------------------------------------------
__global__ void __launch_bounds__(256) gemm_gi(const float* __restrict__ X,
                                               const float* __restrict__ W,
                                               const float* __restrict__ bias) {
    __shared__ float As[32 * 64];
    __shared__ float Bs[32 * 64];
    int tid = threadIdx.x;
    int tx = tid & 15, ty = tid >> 4;
    int rBase = blockIdx.x * 64;
    int n0 = blockIdx.y * 64;
    float acc[4][4];
#pragma unroll
    for (int i = 0; i < 4; i++)
#pragma unroll
        for (int j = 0; j < 4; j++) acc[i][j] = 0.0f;

    for (int kc = 0; kc < 4; kc++) {
        int k0 = kc * 32;
#pragma unroll
        for (int p = 0; p < 2; p++) {
            int l = tid + p * 256;
            int row = l >> 3, q = l & 7;
            int r = rBase + row;
            const float* xp = X + (((size_t)(r & 255) * 512 + (r >> 8)) << 7);
            float4 v = *(const float4*)&xp[k0 + q * 4];
            As[(q * 4 + 0) * 64 + row] = v.x;
            As[(q * 4 + 1) * 64 + row] = v.y;
            As[(q * 4 + 2) * 64 + row] = v.z;
            As[(q * 4 + 3) * 64 + row] = v.w;
        }
#pragma unroll
        for (int p = 0; p < 2; p++) {
            int l = tid + p * 256;
            int n = l >> 3, q = l & 7;
            float4 v = *(const float4*)&W[(size_t)(n0 + n) * 128 + k0 + q * 4];
            Bs[(q * 4 + 0) * 64 + n] = v.x;
            Bs[(q * 4 + 1) * 64 + n] = v.y;
            Bs[(q * 4 + 2) * 64 + n] = v.z;
            Bs[(q * 4 + 3) * 64 + n] = v.w;
        }
        __syncthreads();
#pragma unroll
        for (int kk = 0; kk < 32; kk++) {
            float4 a = *(const float4*)&As[kk * 64 + ty * 4];
            float4 b = *(const float4*)&Bs[kk * 64 + tx * 4];
            acc[0][0] = fmaf(a.x, b.x, acc[0][0]); acc[0][1] = fmaf(a.x, b.y, acc[0][1]);
            acc[0][2] = fmaf(a.x, b.z, acc[0][2]); acc[0][3] = fmaf(a.x, b.w, acc[0][3]);
            acc[1][0] = fmaf(a.y, b.x, acc[1][0]); acc[1][1] = fmaf(a.y, b.y, acc[1][1]);
            acc[1][2] = fmaf(a.y, b.z, acc[1][2]); acc[1][3] = fmaf(a.y, b.w, acc[1][3]);
            acc[2][0] = fmaf(a.z, b.x, acc[2][0]); acc[2][1] = fmaf(a.z, b.y, acc[2][1]);
            acc[2][2] = fmaf(a.z, b.z, acc[2][2]); acc[2][3] = fmaf(a.z, b.w, acc[2][3]);
            acc[3][0] = fmaf(a.w, b.x, acc[3][0]); acc[3][1] = fmaf(a.w, b.y, acc[3][1]);
            acc[3][2] = fmaf(a.w, b.z, acc[3][2]); acc[3][3] = fmaf(a.w, b.w, acc[3][3]);
        }
        __syncthreads();
    }
    float b0 = bias[n0 + tx * 4 + 0], b1 = bias[n0 + tx * 4 + 1];
    float b2 = bias[n0 + tx * 4 + 2], b3 = bias[n0 + tx * 4 + 3];
#pragma unroll
    for (int i = 0; i < 4; i++) {
        int r = rBase + ty * 4 + i;
        float4 v = make_float4(acc[i][0] + b0, acc[i][1] + b1, acc[i][2] + b2, acc[i][3] + b3);
        *(float4*)&g_Genc[(size_t)r * 384 + n0 + tx * 4] = v;
    }
}

// ---------------------------------------------------------------------------
// out-GEMM (R5-exact): o_i = Hdec[i] @ out_W^T + out_b ; writes output[b][511-i][:]
// Launch dim3(2048, 2).
// ---------------------------------------------------------------------------
__global__ void __launch_bounds__(256) gemm_out(const float* __restrict__ W,
                                                const float* __restrict__ bias,
                                                float* __restrict__ out) {
    __shared__ float As[32 * 64];
    __shared__ float Bs[32 * 64];
    int tid = threadIdx.x;
    int tx = tid & 15, ty = tid >> 4;
    int rBase = blockIdx.x * 64;
    int n0 = blockIdx.y * 64;
    float acc[4][4];
#pragma unroll
    for (int i = 0; i < 4; i++)
#pragma unroll
        for (int j = 0; j < 4; j++) acc[i][j] = 0.0f;

    for (int kc = 0; kc < 4; kc++) {
        int k0 = kc * 32;
#pragma unroll
        for (int p = 0; p < 2; p++) {
            int l = tid + p * 256;
            int row = l >> 3, q = l & 7;
            int r = rBase + row;
            float4 v = *(const float4*)&g_Hdec[(size_t)r * 128 + k0 + q * 4];
            As[(q * 4 + 0) * 64 + row] = v.x;
            As[(q * 4 + 1) * 64 + row] = v.y;
            As[(q * 4 + 2) * 64 + row] = v.z;
            As[(q * 4 + 3) * 64 + row] = v.w;
        }
#pragma unroll
        for (int p = 0; p < 2; p++) {
            int l = tid + p * 256;
            int n = l >> 3, q = l & 7;
            float4 v = *(const float4*)&W[(size_t)(n0 + n) * 128 + k0 + q * 4];
            Bs[(q * 4 + 0) * 64 + n] = v.x;
            Bs[(q * 4 + 1) * 64 + n] = v.y;
            Bs[(q * 4 + 2) * 64 + n] = v.z;
            Bs[(q * 4 + 3) * 64 + n] = v.w;
        }
        __syncthreads();
#pragma unroll
        for (int kk = 0; kk < 32; kk++) {
            float4 a = *(const float4*)&As[kk * 64 + ty * 4];
            float4 b = *(const float4*)&Bs[kk * 64 + tx * 4];
            acc[0][0] = fmaf(a.x, b.x, acc[0][0]); acc[0][1] = fmaf(a.x, b.y, acc[0][1]);
            acc[0][2] = fmaf(a.x, b.z, acc[0][2]); acc[0][3] = fmaf(a.x, b.w, acc[0][3]);
            acc[1][0] = fmaf(a.y, b.x, acc[1][0]); acc[1][1] = fmaf(a.y, b.y, acc[1][1]);
            acc[1][2] = fmaf(a.y, b.z, acc[1][2]); acc[1][3] = fmaf(a.y, b.w, acc[1][3]);
            acc[2][0] = fmaf(a.z, b.x, acc[2][0]); acc[2][1] = fmaf(a.z, b.y, acc[2][1]);
            acc[2][2] = fmaf(a.z, b.z, acc[2][2]); acc[2][3] = fmaf(a.z, b.w, acc[2][3]);
            acc[3][0] = fmaf(a.w, b.x, acc[3][0]); acc[3][1] = fmaf(a.w, b.y, acc[3][1]);
            acc[3][2] = fmaf(a.w, b.z, acc[3][2]); acc[3][3] = fmaf(a.w, b.w, acc[3][3]);
        }
        __syncthreads();
    }
    float b0 = bias[n0 + tx * 4 + 0], b1 = bias[n0 + tx * 4 + 1];
    float b2 = bias[n0 + tx * 4 + 2], b3 = bias[n0 + tx * 4 + 3];
#pragma unroll
    for (int i = 0; i < 4; i++) {
        int r = rBase + ty * 4 + i;
        int is = r >> 8, bb = r & 255;
        size_t orow = (size_t)(bb * 512 + (511 - is)) * 128;
        float4 v = make_float4(acc[i][0] + b0, acc[i][1] + b1, acc[i][2] + b2, acc[i][3] + b3);
        *(float4*)&out[OFF_OUT + orow + n0 + tx * 4] = v;
    }
}

// ---------------------------------------------------------------------------
// Fold: Mf[g][j] = sum_f dec_Wih[g,f]*out_W[f,j];  bf[g] = dec_bih[g] + dec_Wih[g,:].out_b
// ---------------------------------------------------------------------------
__global__ void fold_kernel(const float* __restrict__ dWih, const float* __restrict__ outW,
                            const float* __restrict__ outb, const float* __restrict__ dbih) {
    int g = blockIdx.x, j = threadIdx.x;
    __shared__ float wrow[128];
    __shared__ float red[128];
    wrow[j] = dWih[g * 128 + j];
    __syncthreads();
    float acc = 0.0f;
#pragma unroll 8
    for (int f = 0; f < 128; f++) acc = fmaf(wrow[f], outW[f * 128 + j], acc);
    g_Mf[g * 128 + j] = acc;
    red[j] = wrow[j] * outb[j];
    __syncthreads();
    for (int s = 64; s > 0; s >>= 1) {
        if (j < s) red[j] += red[j + s];
        __syncthreads();
    }
    if (j == 0) g_bf[g] = dbih[g] + red[0];
}

// ---------------------------------------------------------------------------
// Encoder recurrence (R5-exact scalar): 128 CTAs x 384 threads; 2 batch/CTA.
// Thread g holds Whh row g in registers (float w[128]).
// ---------------------------------------------------------------------------
__global__ void __launch_bounds__(384, 1) enc_kernel(const float* __restrict__ Whh,
                                                     const float* __restrict__ bhh) {
    __shared__ float h_sm[2][128];
    __shared__ float gh_sm[2][384];
    int g = threadIdx.x;
    int b0 = blockIdx.x * 2;
    float w[128];
#pragma unroll
    for (int k = 0; k < 128; k += 4) {
        float4 v = *(const float4*)&Whh[(size_t)g * 128 + k];
        w[k] = v.x; w[k + 1] = v.y; w[k + 2] = v.z; w[k + 3] = v.w;
    }
    float bg = bhh[g];
    int bb = g >> 7, j = g & 127;
    if (g < 256) h_sm[bb][j] = 0.0f;
    __syncthreads();

    for (int t = 0; t < 512; t++) {
        float gi_r = 0.f, gi_z = 0.f, gi_n = 0.f;
        if (g < 256) {
            const float* gp = g_Genc + ((size_t)t * 256 + b0 + bb) * 384;
            gi_r = gp[j]; gi_z = gp[128 + j]; gi_n = gp[256 + j];
        }
        float a0 = bg, a1 = bg;
#pragma unroll
        for (int k = 0; k < 128; k += 4) {
            float4 h0 = *(const float4*)&h_sm[0][k];
            float4 h1 = *(const float4*)&h_sm[1][k];
            a0 = fmaf(w[k], h0.x, a0);     a1 = fmaf(w[k], h1.x, a1);
            a0 = fmaf(w[k + 1], h0.y, a0); a1 = fmaf(w[k + 1], h1.y, a1);
            a0 = fmaf(w[k + 2], h0.z, a0); a1 = fmaf(w[k + 2], h1.z, a1);
            a0 = fmaf(w[k + 3], h0.w, a0); a1 = fmaf(w[k + 3], h1.w, a1);
        }
        gh_sm[0][g] = a0;
        gh_sm[1][g] = a1;
        __syncthreads();
        if (g < 256) {
            float r = sigf(gi_r + gh_sm[bb][j]);
            float z = sigf(gi_z + gh_sm[bb][128 + j]);
            float n = tanhf(gi_n + r * gh_sm[bb][256 + j]);
            h_sm[bb][j] = (1.0f - z) * n + z * h_sm[bb][j];
        }
        __syncthreads();
    }
    if (g < 256) g_Henc[(b0 + bb) * 128 + j] = h_sm[bb][j];
}

// ---------------------------------------------------------------------------
// Decoder recurrence (R7-exact, best measured 955.8us). Mf in regs (64 ull),
// dec_Whh streamed from smem as ulonglong2 wq[32][384]; grouped loads/gi/gh.
// ---------------------------------------------------------------------------
__global__ void __launch_bounds__(384, 1) dec_kernel(const float* __restrict__ Whh,
                                                     const float* __restrict__ bhh) {
    extern __shared__ __align__(16) unsigned char dsm[];
    ulonglong2* wq = (ulonglong2*)dsm;                 // [32][384] -> 196608 B
    float* hsm = (float*)(dsm + 196608);               // [2][128]
    float* gis = hsm + 256;                            // [2][384]
    float* ghs = gis + 768;                            // [2][384]
    int g = threadIdx.x;
    int b0 = blockIdx.x * 2;
    int bb = g >> 7, j = g & 127;

    ull w2[64];
    {
        const ull* wrow = (const ull*)g_Mf + (size_t)g * 64;
#pragma unroll
        for (int kp = 0; kp < 64; kp++) w2[kp] = wrow[kp];
    }
    float bfg = g_bf[g];
    float bhg = bhh[g];

    for (int idx = g; idx < 384 * 32; idx += 384) {
        int gg = idx >> 5, q = idx & 31;
        wq[q * 384 + gg] = ((const ulonglong2*)Whh)[(size_t)gg * 32 + q];
    }
    if (g < 256) {
        float h_init = g_Henc[b0 * 128 + g];
        hsm[g] = h_init;
        g_Hdec[((size_t)0 * 256 + b0 + bb) * 128 + j] = h_init;
    }
    __syncthreads();

    for (int i = 0; i < 512; i++) {
        ull gi0 = pk2(bfg, 0.f), gi1 = pk2(bfg, 0.f);
        ull gh0 = pk2(bhg, 0.f), gh1 = pk2(bhg, 0.f);
#pragma unroll
        for (int grp = 0; grp < 16; grp++) {
            ulonglong2 wvA = wq[(2 * grp) * 384 + g];
            ulonglong2 wvB = wq[(2 * grp + 1) * 384 + g];
            ulonglong2 h0A = *(const ulonglong2*)&hsm[8 * grp];
            ulonglong2 h0B = *(const ulonglong2*)&hsm[8 * grp + 4];
            ulonglong2 h1A = *(const ulonglong2*)&hsm[128 + 8 * grp];
            ulonglong2 h1B = *(const ulonglong2*)&hsm[128 + 8 * grp + 4];
            gi0 = f2fma(w2[4 * grp],     h0A.x, gi0);
            gi1 = f2fma(w2[4 * grp],     h1A.x, gi1);
            gi0 = f2fma(w2[4 * grp + 1], h0A.y, gi0);
            gi1 = f2fma(w2[4 * grp + 1], h1A.y, gi1);
            gi0 = f2fma(w2[4 * grp + 2], h0B.x, gi0);
            gi1 = f2fma(w2[4 * grp + 2], h1B.x, gi1);
            gi0 = f2fma(w2[4 * grp + 3], h0B.y, gi0);
            gi1 = f2fma(w2[4 * grp + 3], h1B.y, gi1);
            gh0 = f2fma(wvA.x, h0A.x, gh0);
            gh1 = f2fma(wvA.x, h1A.x, gh1);
            gh0 = f2fma(wvA.y, h0A.y, gh0);
            gh1 = f2fma(wvA.y, h1A.y, gh1);
            gh0 = f2fma(wvB.x, h0B.x, gh0);
            gh1 = f2fma(wvB.x, h1B.x, gh1);
            gh0 = f2fma(wvB.y, h0B.y, gh0);
            gh1 = f2fma(wvB.y, h1B.y, gh1);
        }
        gis[g] = psum(gi0); gis[384 + g] = psum(gi1);
        ghs[g] = psum(gh0); ghs[384 + g] = psum(gh1);
        __syncthreads();
        if (g < 256) {
            int base = bb * 384;
            float r = sigf(gis[base + j] + ghs[base + j]);
            float z = sigf(gis[base + 128 + j] + ghs[base + 128 + j]);
            float n = tanhf(gis[base + 256 + j] + r * ghs[base + 256 + j]);
            float h_new = (1.0f - z) * n + z * hsm[g];
            hsm[g] = h_new;
            if (i < 511)
                g_Hdec[((size_t)(i + 1) * 256 + b0 + bb) * 128 + j] = h_new;
        }
        __syncthreads();
    }
}

// ---------------------------------------------------------------------------
// Epilogue A: cosine, h_enc copy, LN/attn/dis/z/gamma. One block per batch elem.
// ---------------------------------------------------------------------------
__device__ __forceinline__ float bsum(float v, float* red) {
    int t = threadIdx.x;
    __syncthreads();
    red[t] = v;
    __syncthreads();
    for (int s = 128; s > 0; s >>= 1) {
        if (t < s) red[t] += red[t + s];
        __syncthreads();
    }
    return red[0];
}

__global__ void __launch_bounds__(256) epiA(
    const float* __restrict__ X,
    const float* __restrict__ protos,
    const float* __restrict__ lnzw, const float* __restrict__ lnzb,
    const float* __restrict__ lnpw, const float* __restrict__ lnpb,
    const float* __restrict__ lnaw, const float* __restrict__ lnab,
    const float* __restrict__ beta,
    const float* __restrict__ e1W, const float* __restrict__ e1b,
    const float* __restrict__ e2W, const float* __restrict__ e2b,
    float* __restrict__ out) {
    int b = blockIdx.x, t = threadIdx.x;
    __shared__ float red[256];
    __shared__ float zln[128];
    __shared__ float pl[8][128];
    __shared__ float dotk[8];
    __shared__ float attnv[8];
    __shared__ float zfull[129];
    __shared__ float h1s[10];
    __shared__ float lg[4];

    const float* a = X + (size_t)b * 65536;
    const float* o = out + OFF_OUT + (size_t)b * 65536;
    float sab = 0.f, saa = 0.f, sbb = 0.f;
    for (int i = t; i < 65536; i += 256) {
        float av = a[i], bv = o[i];
        sab = fmaf(av, bv, sab);
        saa = fmaf(av, av, saa);
        sbb = fmaf(bv, bv, sbb);
    }
    sab = bsum(sab, red);
    saa = bsum(saa, red);
    sbb = bsum(sbb, red);
    float rc = sab / (fmaxf(sqrtf(saa), 1e-8f) * fmaxf(sqrtf(sbb), 1e-8f));

    float h = (t < 128) ? g_Henc[b * 128 + t] : 0.0f;
    if (t < 128) out[OFF_HENC + b * 128 + t] = h;
    float mu = bsum(h, red) * (1.0f / 128.0f);
    float d = (t < 128) ? (h - mu) : 0.0f;
    float var = bsum(d * d, red) * (1.0f / 128.0f);
    if (t < 128) zln[t] = lnzw[t] * d * rsqrtf(var + 1e-12f) + lnzb[t];

    for (int k = 0; k < 8; k++) {
        float p = (t < 128) ? protos[k * 128 + t] : 0.0f;
        float pu = bsum(p, red) * (1.0f / 128.0f);
        float pd = (t < 128) ? (p - pu) : 0.0f;
        float pv = bsum(pd * pd, red) * (1.0f / 128.0f);
        if (t < 128) pl[k][t] = lnpw[t] * pd * rsqrtf(pv + 1e-12f) + lnpb[t];
    }
    __syncthreads();

    for (int k = 0; k < 8; k++) {
        float pp = (t < 128) ? zln[t] * pl[k][t] : 0.0f;
        float s = bsum(pp, red);
        if (t == 0) dotk[k] = s * 0.08838834764831845f;
    }
    __syncthreads();
    if (t < 8) {
        float m = -1e30f;
        for (int kk = 0; kk < 8; kk++) m = fmaxf(m, dotk[kk]);
        float s = 0.f;
        for (int kk = 0; kk < 8; kk++) s += expf(dotk[kk] - m);
        attnv[t] = expf(dotk[t] - m) / s;
    }
    __syncthreads();

    float zacc = 0.0f;
    for (int k = 0; k < 8; k++) {
        float v = (t < 128) ? (beta[k * 128 + t] + attnv[k] * h) : 0.0f;
        float vu = bsum(v, red) * (1.0f / 128.0f);
        float vd = (t < 128) ? (v - vu) : 0.0f;
        float vv = bsum(vd * vd, red) * (1.0f / 128.0f);
        if (t < 128) {
            float dval = lnaw[t] * vd * rsqrtf(vv + 1e-12f) + lnab[t];
            out[OFF_DIS + ((size_t)b * 8 + k) * 128 + t] = dval;
            zacc += dval;
        }
    }
    if (t < 128) {
        float zv = zacc * 0.125f;
        zfull[t] = zv;
        out[OFF_Z + (size_t)b * 129 + t] = zv;
    }
    if (t == 0) {
        zfull[128] = rc;
        out[OFF_Z + (size_t)b * 129 + 128] = rc;
    }
    __syncthreads();

    if (t < 10) {
        float acc = e1b[t];
        for (int i = 0; i < 129; i++) acc = fmaf(e1W[t * 129 + i], zfull[i], acc);
        h1s[t] = tanhf(acc);
    }
    __syncthreads();
    if (t < 4) {
        float acc = e2b[t];
        for (int i = 0; i < 10; i++) acc = fmaf(e2W[t * 10 + i], h1s[i], acc);
        lg[t] = acc;
    }
    __syncthreads();
    if (t < 4) {
        float m = fmaxf(fmaxf(lg[0], lg[1]), fmaxf(lg[2], lg[3]));
        float s = expf(lg[0] - m) + expf(lg[1] - m) + expf(lg[2] - m) + expf(lg[3] - m);
        out[OFF_GAMMA + (size_t)b * 4 + t] = expf(lg[t] - m) / s;
    }
}

// dis_perm[b,k,:] = dis[perm_k[b], k, :]
__global__ void epiB(float* __restrict__ out, const int* __restrict__ perm) {
    int b = blockIdx.x;
    for (int e = threadIdx.x; e < 1024; e += blockDim.x) {
        int k = e >> 7, j = e & 127;
        int src = perm[k * 256 + b];
        out[OFF_DISP + ((size_t)b * 8 + k) * 128 + j] =
            out[OFF_DIS + ((size_t)src * 8 + k) * 128 + j];
    }
}

// ---------------------------------------------------------------------------
extern "C" void kernel_launch(void* const* d_in, const int* in_sizes, int n_in,
                              void* d_out, int out_size) {
    const float* input   = (const float*)d_in[0];
    const float* enc_Wih = (const float*)d_in[1];
    const float* enc_Whh = (const float*)d_in[2];
    const float* enc_bih = (const float*)d_in[3];
    const float* enc_bhh = (const float*)d_in[4];
    const float* dec_Wih = (const float*)d_in[5];
    const float* dec_Whh = (const float*)d_in[6];
    const float* dec_bih = (const float*)d_in[7];
    const float* dec_bhh = (const float*)d_in[8];
    const float* out_W   = (const float*)d_in[9];
    const float* out_b   = (const float*)d_in[10];
    const float* protos  = (const float*)d_in[11];
    const float* lnz_w   = (const float*)d_in[12];
    const float* lnz_b   = (const float*)d_in[13];
    const float* lnp_w   = (const float*)d_in[14];
    const float* lnp_b   = (const float*)d_in[15];
    const float* lna_w   = (const float*)d_in[16];
    const float* lna_b   = (const float*)d_in[17];
    const float* beta    = (const float*)d_in[18];
    const float* est1_W  = (const float*)d_in[19];
    const float* est1_b  = (const float*)d_in[20];
    const float* est2_W  = (const float*)d_in[21];
    const float* est2_b  = (const float*)d_in[22];
    float* out = (float*)d_out;

    int* perm_ptr = nullptr;
    cudaGetSymbolAddress((void**)&perm_ptr, g_perm);

    cudaFuncSetAttribute(dec_kernel, cudaFuncAttributeMaxDynamicSharedMemorySize, 204288);

    // 1. Encoder input gates (time-parallel GEMM; R5 grid)
    gemm_gi<<<dim3(2048, 6), 256>>>(input, enc_Wih, enc_bih);
    // 2. Encoder recurrence (R5 scalar, register weights)
    enc_kernel<<<128, 384>>>(enc_Whh, enc_bhh);
    // 3. Fold output projection into decoder input weights
    fold_kernel<<<384, 128>>>(dec_Wih, out_W, out_b, dec_bih);
    // 4. Decoder recurrence (R7 best: Mf regs + Whh smem stream)
    dec_kernel<<<128, 384, 204288>>>(dec_Whh, dec_bhh);
    // 5. Output projection for all 512 steps (parallel GEMM; R5 grid)
    gemm_out<<<dim3(2048, 2), 256>>>(out_W, out_b, out);
    // 6. JAX-exact permutations
    perm_kernel<<<1, 256>>>(perm_ptr);
    // 7. Epilogue: cosine, LN, attention, dis, z, gamma
    epiA<<<256, 256>>>(input, protos, lnz_w, lnz_b, lnp_w, lnp_b, lna_w, lna_b,
                       beta, est1_W, est1_b, est2_W, est2_b, out);
    // 8. dis_perm gather
    epiB<<<256, 256>>>(out, perm_ptr);
}

// round 12
// speedup vs baseline: 2.4023x; 1.1039x over previous
#include <cuda_runtime.h>
#include <cuda_bf16.h>
#include <math.h>
#include <stdint.h>
#include <stddef.h>

// Problem dims
#define Bsz 256
#define Ssz 512
#define Fdim 128
#define Hdim 128
#define G3  384   // 3*H

// Output layout (tuple flattened): h_enc, output, z, gamma, dis, dis_perm
#define OFF_HENC  ((size_t)0)
#define OFF_OUT   ((size_t)32768)                       // 256*128
#define OFF_Z     ((size_t)(32768 + 16777216))          // + 256*512*128
#define OFF_GAMMA ((size_t)(OFF_Z + 256*129))
#define OFF_DIS   ((size_t)(OFF_GAMMA + 256*4))
#define OFF_DISP  ((size_t)(OFF_DIS + 256*8*128))

typedef unsigned long long ull;

// Scratch (device globals; no allocations allowed)
__device__ float g_Genc[(size_t)Ssz * Bsz * G3];    // [t][b][g]  192 MB
__device__ float g_Hdec[(size_t)Ssz * Bsz * Hdim];  // [i][b][j]   64 MB
__device__ float g_Henc[Bsz * Hdim];
__device__ float g_Mf[G3 * Hdim];
__device__ float g_bf[G3];
__device__ int   g_perm[8 * Bsz];
// bf16 split operands for the tensor-core gi GEMM
__device__ __nv_bfloat16 g_Xh[(size_t)131072 * 128];   // 33.5 MB
__device__ __nv_bfloat16 g_Xl[(size_t)131072 * 128];
__device__ __nv_bfloat16 g_Wh[G3 * 128];
__device__ __nv_bfloat16 g_Wl[G3 * 128];

__device__ __forceinline__ float sigf(float x) { return 1.0f / (1.0f + expf(-x)); }

// ---- packed f32x2 helpers (used by dec only) ----
__device__ __forceinline__ ull pk2(float lo, float hi) {
    ull r; asm("mov.b64 %0, {%1, %2};" : "=l"(r) : "f"(lo), "f"(hi)); return r;
}
__device__ __forceinline__ ull f2fma(ull a, ull b, ull c) {
    ull d; asm("fma.rn.f32x2 %0, %1, %2, %3;" : "=l"(d) : "l"(a), "l"(b), "l"(c)); return d;
}
__device__ __forceinline__ float psum(ull v) {
    float a, b; asm("mov.b64 {%0, %1}, %2;" : "=f"(a), "=f"(b) : "l"(v)); return a + b;
}

__device__ __forceinline__ unsigned smaddr(const void* p) {
    unsigned a;
    asm("{ .reg .u64 t; cvta.to.shared.u64 t, %1; cvt.u32.u64 %0, t; }" : "=r"(a) : "l"(p));
    return a;
}

// ldmatrix x4 (sm_75+, portable target)
__device__ __forceinline__ void ldsm4(unsigned* f, unsigned addr) {
    asm volatile("ldmatrix.sync.aligned.m8n8.x4.shared.b16 {%0,%1,%2,%3}, [%4];"
                 : "=r"(f[0]), "=r"(f[1]), "=r"(f[2]), "=r"(f[3]) : "r"(addr));
}
// mma.sync bf16 (sm_80+, portable target)
__device__ __forceinline__ void mma16816(float* d, const unsigned* a, unsigned b0, unsigned b1) {
    asm volatile(
        "mma.sync.aligned.m16n8k16.row.col.f32.bf16.bf16.f32 "
        "{%0,%1,%2,%3}, {%4,%5,%6,%7}, {%8,%9}, {%0,%1,%2,%3};"
        : "+f"(d[0]), "+f"(d[1]), "+f"(d[2]), "+f"(d[3])
        : "r"(a[0]), "r"(a[1]), "r"(a[2]), "r"(a[3]), "r"(b0), "r"(b1));
}

// ---------------------------------------------------------------------------
// Threefry2x32 (exact JAX constants)
// ---------------------------------------------------------------------------
__device__ __forceinline__ uint2 threefry(unsigned k0, unsigned k1,
                                          unsigned x0, unsigned x1) {
    unsigned ks2 = k0 ^ k1 ^ 0x1BD11BDAu;
    x0 += k0; x1 += k1;
#define TFR(r) { x0 += x1; x1 = (x1 << (r)) | (x1 >> (32 - (r))); x1 ^= x0; }
    TFR(13) TFR(15) TFR(26) TFR(6)   x0 += k1;  x1 += ks2 + 1u;
    TFR(17) TFR(29) TFR(16) TFR(24)  x0 += ks2; x1 += k0 + 2u;
    TFR(13) TFR(15) TFR(26) TFR(6)   x0 += k0;  x1 += k1 + 3u;
    TFR(17) TFR(29) TFR(16) TFR(24)  x0 += k1;  x1 += ks2 + 4u;
    TFR(13) TFR(15) TFR(26) TFR(6)   x0 += ks2; x1 += k0 + 5u;
#undef TFR
    return make_uint2(x0, x1);
}

__global__ void perm_kernel(int* __restrict__ perm) {
    __shared__ unsigned sk[8][2];
    __shared__ unsigned bits[256];
    int t = threadIdx.x;
    if (t < 8) {
        uint2 pk = threefry(0u, 42u, 0u, (unsigned)t);
        uint2 s  = threefry(pk.x, pk.y, 0u, 1u);
        sk[t][0] = s.x; sk[t][1] = s.y;
    }
    __syncthreads();
    for (int k = 0; k < 8; k++) {
        uint2 y = threefry(sk[k][0], sk[k][1], 0u, (unsigned)t);
        bits[t] = y.x ^ y.y;
        __syncthreads();
        unsigned mine = bits[t];
        int rank = 0;
        for (int j = 0; j < 256; j++) {
            unsigned o = bits[j];
            rank += (o < mine) || (o == mine && j < t);
        }
        perm[k * 256 + rank] = t;
        __syncthreads();
    }
}

// ---------------------------------------------------------------------------
// bf16 split conversion: X[b][t][k] -> Xh/Xl[(t*256+b)*128+k]; W -> Wh/Wl
// ---------------------------------------------------------------------------
__global__ void conv_x(const float* __restrict__ X) {
    unsigned c = blockIdx.x * blockDim.x + threadIdx.x;
    int k0 = (c & 15) * 8;
    int t = (int)((c >> 4) & 511);
    int b = (int)(c >> 13);
    const float* src = X + (((size_t)b * 512 + t) * 128 + k0);
    size_t dst = ((size_t)(t * 256 + b)) * 128 + k0;
#pragma unroll
    for (int i = 0; i < 8; i++) {
        float x = src[i];
        __nv_bfloat16 h = __float2bfloat16(x);
        g_Xh[dst + i] = h;
        g_Xl[dst + i] = __float2bfloat16(x - __bfloat162float(h));
    }
}

__global__ void conv_w(const float* __restrict__ W) {
    unsigned c = blockIdx.x * blockDim.x + threadIdx.x;
    int k0 = (c & 15) * 8;
    int gt = (int)(c >> 4);
    const float* src = W + ((size_t)gt * 128 + k0);
    size_t dst = (size_t)gt * 128 + k0;
#pragma unroll
    for (int i = 0; i < 8; i++) {
        float x = src[i];
        __nv_bfloat16 h = __float2bfloat16(x);
        g_Wh[dst + i] = h;
        g_Wl[dst + i] = __float2bfloat16(x - __bfloat162float(h));
    }
}

// ---------------------------------------------------------------------------
// HMMA gi GEMM (split-bf16, 3 terms): g_Genc[r][g] = x[r,:].W[g,:] + bias
// mma.sync.m16n8k16 bf16 (portable sm_103 target; no tcgen05).
// CTA: 128 rows x 128 gates. 8 warps (4M x 2N), warp tile 32x64.
// smem rows padded to 136 bf16 (272B) -> ldmatrix conflict-free.
// Grid (3, 1024): N-tiles fastest so each A tile stays L2-resident.
// ---------------------------------------------------------------------------
#define APAD 136
#define MMA_SMEM (4 * 128 * APAD * 2)   // 139264 B

__global__ void __launch_bounds__(256) mma_gemm_gi(const float* __restrict__ bias) {
    extern __shared__ __align__(16) __nv_bfloat16 sm[];
    __nv_bfloat16* sAh = sm;                      // 128*136
    __nv_bfloat16* sAl = sm + 128 * APAD;
    __nv_bfloat16* sBh = sm + 2 * 128 * APAD;
    __nv_bfloat16* sBl = sm + 3 * 128 * APAD;
    __shared__ float bias_s[128];
    int tid = threadIdx.x;
    int wid = tid >> 5, lane = tid & 31;
    int n0 = blockIdx.x * 128;
    size_t rBase = (size_t)blockIdx.y * 128;

    if (tid < 128) bias_s[tid] = bias[n0 + tid];

    // Load A (hi & lo): 2048 chunks of 8 bf16
#pragma unroll
    for (int i = 0; i < 8; i++) {
        int c = tid + i * 256;
        int r = c >> 4, k0 = (c & 15) * 8;
        uint4 vh = *(const uint4*)&g_Xh[(rBase + r) * 128 + k0];
        uint4 vl = *(const uint4*)&g_Xl[(rBase + r) * 128 + k0];
        *(uint4*)&sAh[r * APAD + k0] = vh;
        *(uint4*)&sAl[r * APAD + k0] = vl;
    }
    // Load B (hi & lo)
#pragma unroll
    for (int i = 0; i < 8; i++) {
        int c = tid + i * 256;
        int r = c >> 4, k0 = (c & 15) * 8;
        uint4 vh = *(const uint4*)&g_Wh[(size_t)(n0 + r) * 128 + k0];
        uint4 vl = *(const uint4*)&g_Wl[(size_t)(n0 + r) * 128 + k0];
        *(uint4*)&sBh[r * APAD + k0] = vh;
        *(uint4*)&sBl[r * APAD + k0] = vl;
    }
    __syncthreads();

    int wm = wid >> 1, wn = wid & 1;
    float d[2][8][4];
#pragma unroll
    for (int mf = 0; mf < 2; mf++)
#pragma unroll
        for (int nf = 0; nf < 8; nf++)
#pragma unroll
            for (int e = 0; e < 4; e++) d[mf][nf][e] = 0.0f;

    // ldmatrix lane-address components (see PTX ISA frag layouts)
    int aRow = wm * 32 + (lane & 7) + ((lane >> 3) & 1) * 8;   // + mf*16
    int aCol = (lane >> 4) * 8;                                 // + k0
    int bRow = wn * 64 + (lane & 7) + ((lane >= 16) ? 8 : 0);   // + np*16
    int bCol = ((lane >> 3) & 1) * 8;                           // + k0

    for (int ks = 0; ks < 8; ks++) {
        int k0 = ks * 16;
        unsigned ah[2][4], al[2][4];
#pragma unroll
        for (int mf = 0; mf < 2; mf++) {
            unsigned off = (unsigned)((aRow + mf * 16) * APAD + k0 + aCol) * 2u;
            ldsm4(ah[mf], smaddr(sAh) + off);
            ldsm4(al[mf], smaddr(sAl) + off);
        }
#pragma unroll
        for (int np = 0; np < 4; np++) {
            unsigned off = (unsigned)((bRow + np * 16) * APAD + k0 + bCol) * 2u;
            unsigned bh[4], bl[4];
            ldsm4(bh, smaddr(sBh) + off);
            ldsm4(bl, smaddr(sBl) + off);
#pragma unroll
            for (int mf = 0; mf < 2; mf++) {
                mma16816(d[mf][np * 2],     ah[mf], bh[0], bh[1]);
                mma16816(d[mf][np * 2 + 1], ah[mf], bh[2], bh[3]);
                mma16816(d[mf][np * 2],     ah[mf], bl[0], bl[1]);
                mma16816(d[mf][np * 2 + 1], ah[mf], bl[2], bl[3]);
                mma16816(d[mf][np * 2],     al[mf], bh[0], bh[1]);
                mma16816(d[mf][np * 2 + 1], al[mf], bh[2], bh[3]);
            }
        }
    }

    // Epilogue: D frag mapping -> float2 stores
    int group = lane >> 2, tg = lane & 3;
#pragma unroll
    for (int mf = 0; mf < 2; mf++) {
#pragma unroll
        for (int nf = 0; nf < 8; nf++) {
            int row = wm * 32 + mf * 16 + group;
            int col = wn * 64 + nf * 8 + tg * 2;
            size_t r = rBase + row;
            float b0 = bias_s[col], b1 = bias_s[col + 1];
            float2 v0 = make_float2(d[mf][nf][0] + b0, d[mf][nf][1] + b1);
            float2 v1 = make_float2(d[mf][nf][2] + b0, d[mf][nf][3] + b1);
            *(float2*)&g_Genc[r * 384 + n0 + col] = v0;
            *(float2*)&g_Genc[(r + 8) * 384 + n0 + col] = v1;
        }
    }
}

// ---------------------------------------------------------------------------
// out-GEMM (R5-exact): o_i = Hdec[i] @ out_W^T + out_b ; writes output[b][511-i][:]
// ---------------------------------------------------------------------------
__global__ void __launch_bounds__(256) gemm_out(const float* __restrict__ W,
                                                const float* __restrict__ bias,
                                                float* __restrict__ out) {
    __shared__ float As[32 * 64];
    __shared__ float Bs[32 * 64];
    int tid = threadIdx.x;
    int tx = tid & 15, ty = tid >> 4;
    int rBase = blockIdx.x * 64;
    int n0 = blockIdx.y * 64;
    float acc[4][4];
#pragma unroll
    for (int i = 0; i < 4; i++)
#pragma unroll
        for (int j = 0; j < 4; j++) acc[i][j] = 0.0f;

    for (int kc = 0; kc < 4; kc++) {
        int k0 = kc * 32;
#pragma unroll
        for (int p = 0; p < 2; p++) {
            int l = tid + p * 256;
            int row = l >> 3, q = l & 7;
            int r = rBase + row;
            float4 v = *(const float4*)&g_Hdec[(size_t)r * 128 + k0 + q * 4];
            As[(q * 4 + 0) * 64 + row] = v.x;
            As[(q * 4 + 1) * 64 + row] = v.y;
            As[(q * 4 + 2) * 64 + row] = v.z;
            As[(q * 4 + 3) * 64 + row] = v.w;
        }
#pragma unroll
        for (int p = 0; p < 2; p++) {
            int l = tid + p * 256;
            int n = l >> 3, q = l & 7;
            float4 v = *(const float4*)&W[(size_t)(n0 + n) * 128 + k0 + q * 4];
            Bs[(q * 4 + 0) * 64 + n] = v.x;
            Bs[(q * 4 + 1) * 64 + n] = v.y;
            Bs[(q * 4 + 2) * 64 + n] = v.z;
            Bs[(q * 4 + 3) * 64 + n] = v.w;
        }
        __syncthreads();
#pragma unroll
        for (int kk = 0; kk < 32; kk++) {
            float4 a = *(const float4*)&As[kk * 64 + ty * 4];
            float4 b = *(const float4*)&Bs[kk * 64 + tx * 4];
            acc[0][0] = fmaf(a.x, b.x, acc[0][0]); acc[0][1] = fmaf(a.x, b.y, acc[0][1]);
            acc[0][2] = fmaf(a.x, b.z, acc[0][2]); acc[0][3] = fmaf(a.x, b.w, acc[0][3]);
            acc[1][0] = fmaf(a.y, b.x, acc[1][0]); acc[1][1] = fmaf(a.y, b.y, acc[1][1]);
            acc[1][2] = fmaf(a.y, b.z, acc[1][2]); acc[1][3] = fmaf(a.y, b.w, acc[1][3]);
            acc[2][0] = fmaf(a.z, b.x, acc[2][0]); acc[2][1] = fmaf(a.z, b.y, acc[2][1]);
            acc[2][2] = fmaf(a.z, b.z, acc[2][2]); acc[2][3] = fmaf(a.z, b.w, acc[2][3]);
            acc[3][0] = fmaf(a.w, b.x, acc[3][0]); acc[3][1] = fmaf(a.w, b.y, acc[3][1]);
            acc[3][2] = fmaf(a.w, b.z, acc[3][2]); acc[3][3] = fmaf(a.w, b.w, acc[3][3]);
        }
        __syncthreads();
    }
    float b0 = bias[n0 + tx * 4 + 0], b1 = bias[n0 + tx * 4 + 1];
    float b2 = bias[n0 + tx * 4 + 2], b3 = bias[n0 + tx * 4 + 3];
#pragma unroll
    for (int i = 0; i < 4; i++) {
        int r = rBase + ty * 4 + i;
        int is = r >> 8, bb = r & 255;
        size_t orow = (size_t)(bb * 512 + (511 - is)) * 128;
        float4 v = make_float4(acc[i][0] + b0, acc[i][1] + b1, acc[i][2] + b2, acc[i][3] + b3);
        *(float4*)&out[OFF_OUT + orow + n0 + tx * 4] = v;
    }
}

// ---------------------------------------------------------------------------
// Fold: Mf = dec_Wih @ out_W ; bf = dec_bih + dec_Wih @ out_b
// ---------------------------------------------------------------------------
__global__ void fold_kernel(const float* __restrict__ dWih, const float* __restrict__ outW,
                            const float* __restrict__ outb, const float* __restrict__ dbih) {
    int g = blockIdx.x, j = threadIdx.x;
    __shared__ float wrow[128];
    __shared__ float red[128];
    wrow[j] = dWih[g * 128 + j];
    __syncthreads();
    float acc = 0.0f;
#pragma unroll 8
    for (int f = 0; f < 128; f++) acc = fmaf(wrow[f], outW[f * 128 + j], acc);
    g_Mf[g * 128 + j] = acc;
    red[j] = wrow[j] * outb[j];
    __syncthreads();
    for (int s = 64; s > 0; s >>= 1) {
        if (j < s) red[j] += red[j + s];
        __syncthreads();
    }
    if (j == 0) g_bf[g] = dbih[g] + red[0];
}

// ---------------------------------------------------------------------------
// Encoder recurrence (R5-exact scalar)
// ---------------------------------------------------------------------------
__global__ void __launch_bounds__(384, 1) enc_kernel(const float* __restrict__ Whh,
                                                     const float* __restrict__ bhh) {
    __shared__ float h_sm[2][128];
    __shared__ float gh_sm[2][384];
    int g = threadIdx.x;
    int b0 = blockIdx.x * 2;
    float w[128];
#pragma unroll
    for (int k = 0; k < 128; k += 4) {
        float4 v = *(const float4*)&Whh[(size_t)g * 128 + k];
        w[k] = v.x; w[k + 1] = v.y; w[k + 2] = v.z; w[k + 3] = v.w;
    }
    float bg = bhh[g];
    int bb = g >> 7, j = g & 127;
    if (g < 256) h_sm[bb][j] = 0.0f;
    __syncthreads();

    for (int t = 0; t < 512; t++) {
        float gi_r = 0.f, gi_z = 0.f, gi_n = 0.f;
        if (g < 256) {
            const float* gp = g_Genc + ((size_t)t * 256 + b0 + bb) * 384;
            gi_r = gp[j]; gi_z = gp[128 + j]; gi_n = gp[256 + j];
        }
        float a0 = bg, a1 = bg;
#pragma unroll
        for (int k = 0; k < 128; k += 4) {
            float4 h0 = *(const float4*)&h_sm[0][k];
            float4 h1 = *(const float4*)&h_sm[1][k];
            a0 = fmaf(w[k], h0.x, a0);     a1 = fmaf(w[k], h1.x, a1);
            a0 = fmaf(w[k + 1], h0.y, a0); a1 = fmaf(w[k + 1], h1.y, a1);
            a0 = fmaf(w[k + 2], h0.z, a0); a1 = fmaf(w[k + 2], h1.z, a1);
            a0 = fmaf(w[k + 3], h0.w, a0); a1 = fmaf(w[k + 3], h1.w, a1);
        }
        gh_sm[0][g] = a0;
        gh_sm[1][g] = a1;
        __syncthreads();
        if (g < 256) {
            float r = sigf(gi_r + gh_sm[bb][j]);
            float z = sigf(gi_z + gh_sm[bb][128 + j]);
            float n = tanhf(gi_n + r * gh_sm[bb][256 + j]);
            h_sm[bb][j] = (1.0f - z) * n + z * h_sm[bb][j];
        }
        __syncthreads();
    }
    if (g < 256) g_Henc[(b0 + bb) * 128 + j] = h_sm[bb][j];
}

// ---------------------------------------------------------------------------
// Decoder recurrence (R7-exact, best measured)
// ---------------------------------------------------------------------------
__global__ void __launch_bounds__(384, 1) dec_kernel(const float* __restrict__ Whh,
                                                     const float* __restrict__ bhh) {
    extern __shared__ __align__(16) unsigned char dsm[];
    ulonglong2* wq = (ulonglong2*)dsm;                 // [32][384] -> 196608 B
    float* hsm = (float*)(dsm + 196608);
    float* gis = hsm + 256;
    float* ghs = gis + 768;
    int g = threadIdx.x;
    int b0 = blockIdx.x * 2;
    int bb = g >> 7, j = g & 127;

    ull w2[64];
    {
        const ull* wrow = (const ull*)g_Mf + (size_t)g * 64;
#pragma unroll
        for (int kp = 0; kp < 64; kp++) w2[kp] = wrow[kp];
    }
    float bfg = g_bf[g];
    float bhg = bhh[g];

    for (int idx = g; idx < 384 * 32; idx += 384) {
        int gg = idx >> 5, q = idx & 31;
        wq[q * 384 + gg] = ((const ulonglong2*)Whh)[(size_t)gg * 32 + q];
    }
    if (g < 256) {
        float h_init = g_Henc[b0 * 128 + g];
        hsm[g] = h_init;
        g_Hdec[((size_t)0 * 256 + b0 + bb) * 128 + j] = h_init;
    }
    __syncthreads();

    for (int i = 0; i < 512; i++) {
        ull gi0 = pk2(bfg, 0.f), gi1 = pk2(bfg, 0.f);
        ull gh0 = pk2(bhg, 0.f), gh1 = pk2(bhg, 0.f);
#pragma unroll
        for (int grp = 0; grp < 16; grp++) {
            ulonglong2 wvA = wq[(2 * grp) * 384 + g];
            ulonglong2 wvB = wq[(2 * grp + 1) * 384 + g];
            ulonglong2 h0A = *(const ulonglong2*)&hsm[8 * grp];
            ulonglong2 h0B = *(const ulonglong2*)&hsm[8 * grp + 4];
            ulonglong2 h1A = *(const ulonglong2*)&hsm[128 + 8 * grp];
            ulonglong2 h1B = *(const ulonglong2*)&hsm[128 + 8 * grp + 4];
            gi0 = f2fma(w2[4 * grp],     h0A.x, gi0);
            gi1 = f2fma(w2[4 * grp],     h1A.x, gi1);
            gi0 = f2fma(w2[4 * grp + 1], h0A.y, gi0);
            gi1 = f2fma(w2[4 * grp + 1], h1A.y, gi1);
            gi0 = f2fma(w2[4 * grp + 2], h0B.x, gi0);
            gi1 = f2fma(w2[4 * grp + 2], h1B.x, gi1);
            gi0 = f2fma(w2[4 * grp + 3], h0B.y, gi0);
            gi1 = f2fma(w2[4 * grp + 3], h1B.y, gi1);
            gh0 = f2fma(wvA.x, h0A.x, gh0);
            gh1 = f2fma(wvA.x, h1A.x, gh1);
            gh0 = f2fma(wvA.y, h0A.y, gh0);
            gh1 = f2fma(wvA.y, h1A.y, gh1);
            gh0 = f2fma(wvB.x, h0B.x, gh0);
            gh1 = f2fma(wvB.x, h1B.x, gh1);
            gh0 = f2fma(wvB.y, h0B.y, gh0);
            gh1 = f2fma(wvB.y, h1B.y, gh1);
        }
        gis[g] = psum(gi0); gis[384 + g] = psum(gi1);
        ghs[g] = psum(gh0); ghs[384 + g] = psum(gh1);
        __syncthreads();
        if (g < 256) {
            int base = bb * 384;
            float r = sigf(gis[base + j] + ghs[base + j]);
            float z = sigf(gis[base + 128 + j] + ghs[base + 128 + j]);
            float n = tanhf(gis[base + 256 + j] + r * ghs[base + 256 + j]);
            float h_new = (1.0f - z) * n + z * hsm[g];
            hsm[g] = h_new;
            if (i < 511)
                g_Hdec[((size_t)(i + 1) * 256 + b0 + bb) * 128 + j] = h_new;
        }
        __syncthreads();
    }
}

// ---------------------------------------------------------------------------
// Epilogues (unchanged)
// ---------------------------------------------------------------------------
__device__ __forceinline__ float bsum(float v, float* red) {
    int t = threadIdx.x;
    __syncthreads();
    red[t] = v;
    __syncthreads();
    for (int s = 128; s > 0; s >>= 1) {
        if (t < s) red[t] += red[t + s];
        __syncthreads();
    }
    return red[0];
}

__global__ void __launch_bounds__(256) epiA(
    const float* __restrict__ X,
    const float* __restrict__ protos,
    const float* __restrict__ lnzw, const float* __restrict__ lnzb,
    const float* __restrict__ lnpw, const float* __restrict__ lnpb,
    const float* __restrict__ lnaw, const float* __restrict__ lnab,
    const float* __restrict__ beta,
    const float* __restrict__ e1W, const float* __restrict__ e1b,
    const float* __restrict__ e2W, const float* __restrict__ e2b,
    float* __restrict__ out) {
    int b = blockIdx.x, t = threadIdx.x;
    __shared__ float red[256];
    __shared__ float zln[128];
    __shared__ float pl[8][128];
    __shared__ float dotk[8];
    __shared__ float attnv[8];
    __shared__ float zfull[129];
    __shared__ float h1s[10];
    __shared__ float lg[4];

    const float* a = X + (size_t)b * 65536;
    const float* o = out + OFF_OUT + (size_t)b * 65536;
    float sab = 0.f, saa = 0.f, sbb = 0.f;
    for (int i = t; i < 65536; i += 256) {
        float av = a[i], bv = o[i];
        sab = fmaf(av, bv, sab);
        saa = fmaf(av, av, saa);
        sbb = fmaf(bv, bv, sbb);
    }
    sab = bsum(sab, red);
    saa = bsum(saa, red);
    sbb = bsum(sbb, red);
    float rc = sab / (fmaxf(sqrtf(saa), 1e-8f) * fmaxf(sqrtf(sbb), 1e-8f));

    float h = (t < 128) ? g_Henc[b * 128 + t] : 0.0f;
    if (t < 128) out[OFF_HENC + b * 128 + t] = h;
    float mu = bsum(h, red) * (1.0f / 128.0f);
    float d = (t < 128) ? (h - mu) : 0.0f;
    float var = bsum(d * d, red) * (1.0f / 128.0f);
    if (t < 128) zln[t] = lnzw[t] * d * rsqrtf(var + 1e-12f) + lnzb[t];

    for (int k = 0; k < 8; k++) {
        float p = (t < 128) ? protos[k * 128 + t] : 0.0f;
        float pu = bsum(p, red) * (1.0f / 128.0f);
        float pd = (t < 128) ? (p - pu) : 0.0f;
        float pv = bsum(pd * pd, red) * (1.0f / 128.0f);
        if (t < 128) pl[k][t] = lnpw[t] * pd * rsqrtf(pv + 1e-12f) + lnpb[t];
    }
    __syncthreads();

    for (int k = 0; k < 8; k++) {
        float pp = (t < 128) ? zln[t] * pl[k][t] : 0.0f;
        float s = bsum(pp, red);
        if (t == 0) dotk[k] = s * 0.08838834764831845f;
    }
    __syncthreads();
    if (t < 8) {
        float m = -1e30f;
        for (int kk = 0; kk < 8; kk++) m = fmaxf(m, dotk[kk]);
        float s = 0.f;
        for (int kk = 0; kk < 8; kk++) s += expf(dotk[kk] - m);
        attnv[t] = expf(dotk[t] - m) / s;
    }
    __syncthreads();

    float zacc = 0.0f;
    for (int k = 0; k < 8; k++) {
        float v = (t < 128) ? (beta[k * 128 + t] + attnv[k] * h) : 0.0f;
        float vu = bsum(v, red) * (1.0f / 128.0f);
        float vd = (t < 128) ? (v - vu) : 0.0f;
        float vv = bsum(vd * vd, red) * (1.0f / 128.0f);
        if (t < 128) {
            float dval = lnaw[t] * vd * rsqrtf(vv + 1e-12f) + lnab[t];
            out[OFF_DIS + ((size_t)b * 8 + k) * 128 + t] = dval;
            zacc += dval;
        }
    }
    if (t < 128) {
        float zv = zacc * 0.125f;
        zfull[t] = zv;
        out[OFF_Z + (size_t)b * 129 + t] = zv;
    }
    if (t == 0) {
        zfull[128] = rc;
        out[OFF_Z + (size_t)b * 129 + 128] = rc;
    }
    __syncthreads();

    if (t < 10) {
        float acc = e1b[t];
        for (int i = 0; i < 129; i++) acc = fmaf(e1W[t * 129 + i], zfull[i], acc);
        h1s[t] = tanhf(acc);
    }
    __syncthreads();
    if (t < 4) {
        float acc = e2b[t];
        for (int i = 0; i < 10; i++) acc = fmaf(e2W[t * 10 + i], h1s[i], acc);
        lg[t] = acc;
    }
    __syncthreads();
    if (t < 4) {
        float m = fmaxf(fmaxf(lg[0], lg[1]), fmaxf(lg[2], lg[3]));
        float s = expf(lg[0] - m) + expf(lg[1] - m) + expf(lg[2] - m) + expf(lg[3] - m);
        out[OFF_GAMMA + (size_t)b * 4 + t] = expf(lg[t] - m) / s;
    }
}

__global__ void epiB(float* __restrict__ out, const int* __restrict__ perm) {
    int b = blockIdx.x;
    for (int e = threadIdx.x; e < 1024; e += blockDim.x) {
        int k = e >> 7, j = e & 127;
        int src = perm[k * 256 + b];
        out[OFF_DISP + ((size_t)b * 8 + k) * 128 + j] =
            out[OFF_DIS + ((size_t)src * 8 + k) * 128 + j];
    }
}

// ---------------------------------------------------------------------------
extern "C" void kernel_launch(void* const* d_in, const int* in_sizes, int n_in,
                              void* d_out, int out_size) {
    const float* input   = (const float*)d_in[0];
    const float* enc_Wih = (const float*)d_in[1];
    const float* enc_Whh = (const float*)d_in[2];
    const float* enc_bih = (const float*)d_in[3];
    const float* enc_bhh = (const float*)d_in[4];
    const float* dec_Wih = (const float*)d_in[5];
    const float* dec_Whh = (const float*)d_in[6];
    const float* dec_bih = (const float*)d_in[7];
    const float* dec_bhh = (const float*)d_in[8];
    const float* out_W   = (const float*)d_in[9];
    const float* out_b   = (const float*)d_in[10];
    const float* protos  = (const float*)d_in[11];
    const float* lnz_w   = (const float*)d_in[12];
    const float* lnz_b   = (const float*)d_in[13];
    const float* lnp_w   = (const float*)d_in[14];
    const float* lnp_b   = (const float*)d_in[15];
    const float* lna_w   = (const float*)d_in[16];
    const float* lna_b   = (const float*)d_in[17];
    const float* beta    = (const float*)d_in[18];
    const float* est1_W  = (const float*)d_in[19];
    const float* est1_b  = (const float*)d_in[20];
    const float* est2_W  = (const float*)d_in[21];
    const float* est2_b  = (const float*)d_in[22];
    float* out = (float*)d_out;

    int* perm_ptr = nullptr;
    cudaGetSymbolAddress((void**)&perm_ptr, g_perm);

    cudaFuncSetAttribute(dec_kernel, cudaFuncAttributeMaxDynamicSharedMemorySize, 204288);
    cudaFuncSetAttribute(mma_gemm_gi, cudaFuncAttributeMaxDynamicSharedMemorySize, MMA_SMEM);

    // 1. bf16 split conversion of X and enc_Wih
    conv_x<<<8192, 256>>>(input);
    conv_w<<<24, 256>>>(enc_Wih);
    // 2. Tensor-core gi GEMM (split-bf16, 3 terms, mma.sync)
    mma_gemm_gi<<<dim3(3, 1024), 256, MMA_SMEM>>>(enc_bih);
    // 3. Encoder recurrence
    enc_kernel<<<128, 384>>>(enc_Whh, enc_bhh);
    // 4. Fold output projection into decoder input weights
    fold_kernel<<<384, 128>>>(dec_Wih, out_W, out_b, dec_bih);
    // 5. Decoder recurrence
    dec_kernel<<<128, 384, 204288>>>(dec_Whh, dec_bhh);
    // 6. Output projection for all 512 steps
    gemm_out<<<dim3(2048, 2), 256>>>(out_W, out_b, out);
    // 7. JAX-exact permutations
    perm_kernel<<<1, 256>>>(perm_ptr);
    // 8. Epilogue
    epiA<<<256, 256>>>(input, protos, lnz_w, lnz_b, lnp_w, lnp_b, lna_w, lna_b,
                       beta, est1_W, est1_b, est2_W, est2_b, out);
    // 9. dis_perm gather
    epiB<<<256, 256>>>(out, perm_ptr);
}